// round 13
// baseline (speedup 1.0000x reference)
#include <cuda_runtime.h>
#include <cuda_bf16.h>
#include <math.h>

#define T_STEPS 10
#define B_GR    8
#define NPG     1080
#define N_NODES 8640
#define TN      86400
#define DEG     16

// ---------------- scratch ----------------
__device__ float g_bufA[(size_t)TN * 256];
__device__ float g_bufB[(size_t)TN * 256];
__device__ float g_z[TN * 16];
__device__ __nv_bfloat16 g_W2hi[512 * 256], g_W2lo[512 * 256];
__device__ __nv_bfloat16 g_W3hi[256 * 128], g_W3lo[256 * 128];
__device__ float g_emb[T_STEPS * B_GR * 8];
__device__ float g_uv[32];
__device__ int   g_lsrc[N_NODES * 16];

__device__ __forceinline__ void split_bf16(float x, __nv_bfloat16& h, __nv_bfloat16& l) {
    h = __float2bfloat16_rn(x);
    l = __float2bfloat16_rn(x - __bfloat162float(h));
}

// ---------------- fast exp for x <= 0 ----------------
__device__ __forceinline__ float exp_neg(float x) {
    x = fmaxf(x, -87.0f);
    const float L2E = 1.4426950408889634f;
    float z = fmaf(x, L2E, 12582912.0f);
    int   ei = __float_as_int(z);
    float n = z - 12582912.0f;
    float f = fmaf(x, L2E, -n);
    float r = fmaf(1.5403530e-4f, f, 1.3333558e-3f);
    r = fmaf(r, f, 9.6181291e-3f);
    r = fmaf(r, f, 5.5504109e-2f);
    r = fmaf(r, f, 2.4022651e-1f);
    r = fmaf(r, f, 6.9314718e-1f);
    r = fmaf(r, f, 1.0f);
    float s = __int_as_float((ei + 127) << 23);
    return r * s;
}
__device__ __forceinline__ float elu_f(float v) { return v > 0.f ? v : exp_neg(v) - 1.f; }
__device__ __forceinline__ float lrelu(float e) { return e >= 0.f ? e : 0.2f * e; }

// ---------------- merged setup ----------------
__global__ void setup_all(const int* __restrict__ src, const float* __restrict__ W2,
                          const float* __restrict__ W3, const float* __restrict__ W1,
                          const float* __restrict__ as1, const float* __restrict__ ad1) {
    int bid = blockIdx.x, tid = threadIdx.x;
    if (bid < 540) {
        int i = bid * 256 + tid;
        int b = i / (NPG * 16);
        g_lsrc[i] = src[i] - b * NPG;
    } else if (bid < 1052) {
        int i = (bid - 540) * 256 + tid;
        split_bf16(W2[i], g_W2hi[i], g_W2lo[i]);
    } else if (bid < 1180) {
        int i = (bid - 1052) * 256 + tid;
        split_bf16(W3[i], g_W3hi[i], g_W3lo[i]);
    } else if (tid < 32) {
        int d = tid >> 4, h = (tid >> 1) & 7, f = tid & 1;
        const float* a = d ? ad1 : as1;
        float s = 0.f;
        #pragma unroll
        for (int c = 0; c < 64; c++) s += W1[f * 512 + h * 64 + c] * a[h * 64 + c];
        g_uv[tid] = s;
    }
}

// ---------------- layer 1: x -> z[TN,16] ----------------
__global__ __launch_bounds__(256)
void l1_z(const float* __restrict__ x) {
    __shared__ float xs[NPG * 2];
    __shared__ float es_s[NPG * 8];
    __shared__ float uvS[32];
    int blk = blockIdx.x;
    int chunk = blk & 7;
    int tb = blk >> 3;
    int b = tb & 7, t = tb >> 3;
    int base = t * N_NODES + b * NPG;
    int tid = threadIdx.x;
    if (tid < 32) uvS[tid] = g_uv[tid];
    for (int i = tid; i < NPG * 2; i += 256) xs[i] = x[(size_t)base * 2 + i];
    __syncthreads();
    for (int task = tid; task < NPG * 8; task += 256) {
        int n = task >> 3, h = task & 7;
        es_s[task] = fmaf(xs[n * 2], uvS[h * 2], xs[n * 2 + 1] * uvS[h * 2 + 1]);
    }
    __syncthreads();
    int n0 = chunk * 135;
    for (int task = tid; task < 135 * 8; task += 256) {
        int nl = task >> 3, h = task & 7;
        int n = n0 + nl;
        const int4* ls4 = (const int4*)(g_lsrc + ((size_t)b * NPG + n) * 16);
        int4 iA = ls4[0], iB = ls4[1], iC = ls4[2], iD = ls4[3];
        int idxs[16] = {iA.x, iA.y, iA.z, iA.w, iB.x, iB.y, iB.z, iB.w,
                        iC.x, iC.y, iC.z, iC.w, iD.x, iD.y, iD.z, iD.w};
        float ed = fmaf(xs[n * 2], uvS[16 + h * 2], xs[n * 2 + 1] * uvS[17 + h * 2]);
        float ev[17];
        float m = -1e30f;
        #pragma unroll
        for (int k = 0; k < 16; k++) {
            float e = lrelu(es_s[idxs[k] * 8 + h] + ed);
            ev[k] = e; m = fmaxf(m, e);
        }
        { float e = lrelu(es_s[n * 8 + h] + ed); ev[16] = e; m = fmaxf(m, e); }
        float ssum = 0.f;
        #pragma unroll
        for (int k = 0; k < 17; k++) { float v = exp_neg(ev[k] - m); ev[k] = v; ssum += v; }
        float inv = 1.f / (ssum + 1e-16f);
        float z0 = 0.f, z1 = 0.f;
        #pragma unroll
        for (int k = 0; k < 16; k++) {
            float a = ev[k] * inv;
            z0 = fmaf(a, xs[idxs[k] * 2], z0);
            z1 = fmaf(a, xs[idxs[k] * 2 + 1], z1);
        }
        {
            float a = ev[16] * inv;
            z0 = fmaf(a, xs[n * 2], z0);
            z1 = fmaf(a, xs[n * 2 + 1], z1);
        }
        *(float2*)&g_z[(size_t)(base + n) * 16 + h * 2] = make_float2(z0, z1);
    }
}

// ---------------- GEMM macros ----------------
#define MMA_BF16(d, a, b0, b1) \
    asm volatile("mma.sync.aligned.m16n8k16.row.col.f32.bf16.bf16.f32 " \
        "{%0,%1,%2,%3}, {%4,%5,%6,%7}, {%8,%9}, {%0,%1,%2,%3};" \
        : "+f"(d[0]), "+f"(d[1]), "+f"(d[2]), "+f"(d[3]) \
        : "r"(a[0]), "r"(a[1]), "r"(a[2]), "r"(a[3]), "r"(b0), "r"(b1))

#define LDMX4(r, addr) \
    asm volatile("ldmatrix.sync.aligned.m8n8.x4.shared.b16 {%0,%1,%2,%3}, [%4];" \
        : "=r"(r[0]), "=r"(r[1]), "=r"(r[2]), "=r"(r[3]) : "r"(addr))

#define LDMX4T(r, addr) \
    asm volatile("ldmatrix.sync.aligned.m8n8.x4.trans.shared.b16 {%0,%1,%2,%3}, [%4];" \
        : "=r"(r[0]), "=r"(r[1]), "=r"(r[2]), "=r"(r[3]) : "r"(addr))

#define CP16(dst, src) \
    asm volatile("cp.async.cg.shared.global [%0], [%1], 16;" :: "r"(dst), "l"(src))
#define CP_COMMIT asm volatile("cp.async.commit_group;")
#define CP_WAIT1  asm volatile("cp.async.wait_group 1;")
#define CP_WAIT0  asm volatile("cp.async.wait_group 0;")

#define ASTR 24
#define BSTR2 136

struct alignas(8) US4 { unsigned short v[4]; };

// ---------------- L2 GEMM with A generated from z (single-buffer sA) ----------------
__global__ __launch_bounds__(512)
void l1gemm_bf16(const float* __restrict__ W1, const float* __restrict__ b1,
                 const __nv_bfloat16* __restrict__ Whi, const __nv_bfloat16* __restrict__ Wlo,
                 float* __restrict__ C) {
    const int Nc = 256;
    __shared__ alignas(16) unsigned short sA[2][128 * ASTR];
    __shared__ alignas(16) unsigned short sB[3][2][16 * BSTR2];
    __shared__ float zs[128][16];
    __shared__ float W1s[1024], b1s[512];
    const int tid = threadIdx.x;
    const int lane = tid & 31, wid = tid >> 5;
    const int warpM = wid & 3, warpN = wid >> 2;
    const int rb = blockIdx.y * 128, cb = blockIdx.x * 128;
    const int hl = tid >> 8;
    const int j = tid & 255;
    const int brow = j >> 4, bcol = (j & 15) * 8;
    const __nv_bfloat16* bptr = (hl ? Wlo : Whi) + (size_t)brow * Nc + cb + bcol;
    unsigned sb_dst[3];
    #pragma unroll
    for (int s = 0; s < 3; s++)
        sb_dst[s] = (unsigned)__cvta_generic_to_shared(&sB[s][hl][brow * BSTR2 + bcol]);
    {
        int row = tid >> 2, q = tid & 3;
        *(float4*)&zs[row][q * 4] = *(const float4*)(g_z + (size_t)(rb + row) * 16 + q * 4);
    }
    for (int i = tid; i < 1024; i += 512) W1s[i] = W1[i];
    if (tid < 512) b1s[tid] = b1[tid];
    CP16(sb_dst[0], bptr);
    CP_COMMIT;
    CP16(sb_dst[1], bptr + (size_t)16 * Nc);
    CP_COMMIT;
    __syncthreads();

    const int arow = tid >> 2, ac0 = (tid & 3) * 4;
    const int a_r = (lane & 15);
    const int a_c = (lane >> 4) * 8;
    const int b_k = (lane & 7) + (lane & 8);
    const int b_n = (lane & 16) >> 1;
    float acc[2][4][4] = {};
    const int nk = 32;

    for (int ck = 0; ck < nk; ck++) {
        {
            int h = ck >> 2;
            float z0 = zs[arow][h * 2], z1 = zs[arow][h * 2 + 1];
            US4 hv, lv;
            #pragma unroll
            for (int i = 0; i < 4; i++) {
                int k = ck * 16 + ac0 + i;
                float v = elu_f(fmaf(z0, W1s[k], fmaf(z1, W1s[512 + k], b1s[k])));
                __nv_bfloat16 bh, bl;
                split_bf16(v, bh, bl);
                hv.v[i] = *(unsigned short*)&bh;
                lv.v[i] = *(unsigned short*)&bl;
            }
            *(US4*)&sA[0][arow * ASTR + ac0] = hv;
            *(US4*)&sA[1][arow * ASTR + ac0] = lv;
        }
        if (ck + 1 < nk) { CP_WAIT1; } else { CP_WAIT0; }
        __syncthreads();
        if (ck + 2 < nk) {
            int buf = (ck + 2) % 3;
            CP16(sb_dst[buf], bptr + (size_t)((ck + 2) * 16) * Nc);
            CP_COMMIT;
        }
        int p = ck % 3;
        unsigned ah[2][4], al[2][4];
        #pragma unroll
        for (int ma = 0; ma < 2; ma++) {
            int r = warpM * 32 + ma * 16 + a_r;
            unsigned adh = (unsigned)__cvta_generic_to_shared(&sA[0][r * ASTR + a_c]);
            unsigned adl = (unsigned)__cvta_generic_to_shared(&sA[1][r * ASTR + a_c]);
            LDMX4(ah[ma], adh);
            LDMX4(al[ma], adl);
        }
        unsigned bh[4][2], bl[4][2];
        #pragma unroll
        for (int g = 0; g < 2; g++) {
            int n0 = warpN * 32 + g * 16 + b_n;
            unsigned adh = (unsigned)__cvta_generic_to_shared(&sB[p][0][b_k * BSTR2 + n0]);
            unsigned adl = (unsigned)__cvta_generic_to_shared(&sB[p][1][b_k * BSTR2 + n0]);
            unsigned th[4], tl[4];
            LDMX4T(th, adh);
            LDMX4T(tl, adl);
            bh[g * 2][0] = th[0]; bh[g * 2][1] = th[1];
            bh[g * 2 + 1][0] = th[2]; bh[g * 2 + 1][1] = th[3];
            bl[g * 2][0] = tl[0]; bl[g * 2][1] = tl[1];
            bl[g * 2 + 1][0] = tl[2]; bl[g * 2 + 1][1] = tl[3];
        }
        #pragma unroll
        for (int ma = 0; ma < 2; ma++)
            #pragma unroll
            for (int na = 0; na < 4; na++) {
                MMA_BF16(acc[ma][na], ah[ma], bh[na][0], bh[na][1]);
                MMA_BF16(acc[ma][na], ah[ma], bl[na][0], bl[na][1]);
                MMA_BF16(acc[ma][na], al[ma], bh[na][0], bh[na][1]);
            }
        __syncthreads();
    }
    #pragma unroll
    for (int ma = 0; ma < 2; ma++)
        #pragma unroll
        for (int na = 0; na < 4; na++) {
            int r0 = rb + warpM * 32 + ma * 16 + (lane >> 2);
            int c = cb + warpN * 32 + na * 8 + (lane & 3) * 2;
            *(float2*)(C + (size_t)r0 * Nc + c)       = make_float2(acc[ma][na][0], acc[ma][na][1]);
            *(float2*)(C + (size_t)(r0 + 8) * Nc + c) = make_float2(acc[ma][na][2], acc[ma][na][3]);
        }
}

// ---------------- L3 GEMM: fp32 A split during staging ----------------
__global__ __launch_bounds__(512)
void gemm3_bf16(const float* __restrict__ A,
                const __nv_bfloat16* __restrict__ Whi, const __nv_bfloat16* __restrict__ Wlo,
                float* __restrict__ C) {
    const int K = 256, Nc = 128;
    __shared__ alignas(16) unsigned short sA[2][128 * ASTR];
    __shared__ alignas(16) unsigned short sB[3][2][16 * BSTR2];
    const int tid = threadIdx.x;
    const int lane = tid & 31, wid = tid >> 5;
    const int warpM = wid & 3, warpN = wid >> 2;
    const int rb = blockIdx.y * 128;
    const int hl = tid >> 8;
    const int j = tid & 255;
    const int brow = j >> 4, bcol = (j & 15) * 8;
    const __nv_bfloat16* bptr = (hl ? Wlo : Whi) + (size_t)brow * Nc + bcol;
    unsigned sb_dst[3];
    #pragma unroll
    for (int s = 0; s < 3; s++)
        sb_dst[s] = (unsigned)__cvta_generic_to_shared(&sB[s][hl][brow * BSTR2 + bcol]);
    const int arow = tid >> 2, ac0 = (tid & 3) * 4;
    const float* aptr = A + (size_t)(rb + arow) * K + ac0;
    CP16(sb_dst[0], bptr);
    CP_COMMIT;
    CP16(sb_dst[1], bptr + (size_t)16 * Nc);
    CP_COMMIT;
    float4 areg = *(const float4*)(aptr);
    const int a_r = (lane & 15);
    const int a_c = (lane >> 4) * 8;
    const int b_k = (lane & 7) + (lane & 8);
    const int b_n = (lane & 16) >> 1;
    float acc[2][4][4] = {};
    const int nk = 16;

    for (int ck = 0; ck < nk; ck++) {
        {
            US4 hv, lv;
            float vals[4] = {areg.x, areg.y, areg.z, areg.w};
            #pragma unroll
            for (int i = 0; i < 4; i++) {
                __nv_bfloat16 bh, bl;
                split_bf16(vals[i], bh, bl);
                hv.v[i] = *(unsigned short*)&bh;
                lv.v[i] = *(unsigned short*)&bl;
            }
            *(US4*)&sA[0][arow * ASTR + ac0] = hv;
            *(US4*)&sA[1][arow * ASTR + ac0] = lv;
        }
        if (ck + 1 < nk) { CP_WAIT1; } else { CP_WAIT0; }
        __syncthreads();
        if (ck + 1 < nk) areg = *(const float4*)(aptr + (ck + 1) * 16);
        if (ck + 2 < nk) {
            int buf = (ck + 2) % 3;
            CP16(sb_dst[buf], bptr + (size_t)((ck + 2) * 16) * Nc);
            CP_COMMIT;
        }
        int p = ck % 3;
        unsigned ah[2][4], al[2][4];
        #pragma unroll
        for (int ma = 0; ma < 2; ma++) {
            int r = warpM * 32 + ma * 16 + a_r;
            unsigned adh = (unsigned)__cvta_generic_to_shared(&sA[0][r * ASTR + a_c]);
            unsigned adl = (unsigned)__cvta_generic_to_shared(&sA[1][r * ASTR + a_c]);
            LDMX4(ah[ma], adh);
            LDMX4(al[ma], adl);
        }
        unsigned bh[4][2], bl[4][2];
        #pragma unroll
        for (int g = 0; g < 2; g++) {
            int n0 = warpN * 32 + g * 16 + b_n;
            unsigned adh = (unsigned)__cvta_generic_to_shared(&sB[p][0][b_k * BSTR2 + n0]);
            unsigned adl = (unsigned)__cvta_generic_to_shared(&sB[p][1][b_k * BSTR2 + n0]);
            unsigned th[4], tl[4];
            LDMX4T(th, adh);
            LDMX4T(tl, adl);
            bh[g * 2][0] = th[0]; bh[g * 2][1] = th[1];
            bh[g * 2 + 1][0] = th[2]; bh[g * 2 + 1][1] = th[3];
            bl[g * 2][0] = tl[0]; bl[g * 2][1] = tl[1];
            bl[g * 2 + 1][0] = tl[2]; bl[g * 2 + 1][1] = tl[3];
        }
        #pragma unroll
        for (int ma = 0; ma < 2; ma++)
            #pragma unroll
            for (int na = 0; na < 4; na++) {
                MMA_BF16(acc[ma][na], ah[ma], bh[na][0], bh[na][1]);
                MMA_BF16(acc[ma][na], ah[ma], bl[na][0], bl[na][1]);
                MMA_BF16(acc[ma][na], al[ma], bh[na][0], bh[na][1]);
            }
        __syncthreads();
    }
    #pragma unroll
    for (int ma = 0; ma < 2; ma++)
        #pragma unroll
        for (int na = 0; na < 4; na++) {
            int r0 = rb + warpM * 32 + ma * 16 + (lane >> 2);
            int c = warpN * 32 + na * 8 + (lane & 3) * 2;
            *(float2*)(C + (size_t)r0 * Nc + c)       = make_float2(acc[ma][na][0], acc[ma][na][1]);
            *(float2*)(C + (size_t)(r0 + 8) * Nc + c) = make_float2(acc[ma][na][2], acc[ma][na][3]);
        }
}

// ---------------- fully fused GAT, phase-3 quad-pair tasks + int4 indices ----------------
template<int H, int C, bool LSRC_SMEM>
__global__ __launch_bounds__(1024, 1)
void fused_gat(const float* __restrict__ Y, const float* __restrict__ as_,
               const float* __restrict__ ad_, const float* __restrict__ bias,
               float* __restrict__ Xout) {
    extern __shared__ float sm[];
    constexpr int HC = H * C;
    constexpr int Q = C / 4;       // quads per row (8 or 4)
    constexpr int G = Q / 2;       // quad-pair groups per row
    float* tile   = sm;
    float* es_s   = tile + NPG * C;
    float* ed_s   = es_s + NPG;
    float* alphaS = ed_s + NPG;
    int*   lsrcS  = (int*)(alphaS + NPG * 17);
    __shared__ float as_s[C], ad_s[C], bi_s[C];
    int blk = blockIdx.x;
    int h = blk % H;
    int tb = blk / H;
    int b = tb % B_GR;
    int t = tb / B_GR;
    int base = t * N_NODES + b * NPG;
    int tid = threadIdx.x;
    const int* lg = g_lsrc + (size_t)b * NPG * 16;
    if (tid < C) { as_s[tid] = as_[h * C + tid]; ad_s[tid] = ad_[h * C + tid]; bi_s[tid] = bias[h * C + tid]; }
    for (int i = tid; i < NPG * Q; i += blockDim.x) {
        int n = i / Q, q = i % Q;
        *(float4*)&tile[n * C + q * 4] =
            *(const float4*)(Y + (size_t)(base + n) * HC + h * C + q * 4);
    }
    if (LSRC_SMEM) {
        for (int i = tid; i < NPG * 4; i += blockDim.x)
            ((int4*)lsrcS)[i] = ((const int4*)lg)[i];
    }
    __syncthreads();
    // phase 1: es/ed
    for (int n = tid; n < NPG; n += blockDim.x) {
        const float* tn = tile + n * C;
        int rot1 = tid & (Q - 1);
        float se = 0.f, de = 0.f;
        #pragma unroll
        for (int jj = 0; jj < Q; jj++) {
            int q = (jj + rot1) & (Q - 1);
            float4 v = *(const float4*)&tn[q * 4];
            float4 a = *(const float4*)&as_s[q * 4];
            float4 d = *(const float4*)&ad_s[q * 4];
            se = fmaf(v.x, a.x, fmaf(v.y, a.y, fmaf(v.z, a.z, fmaf(v.w, a.w, se))));
            de = fmaf(v.x, d.x, fmaf(v.y, d.y, fmaf(v.z, d.z, fmaf(v.w, d.w, de))));
        }
        es_s[n] = se; ed_s[n] = de;
    }
    __syncthreads();
    // phase 2: softmax -> alphaS
    for (int n = tid; n < NPG; n += blockDim.x) {
        const int4* ls4 = LSRC_SMEM ? (const int4*)(lsrcS + n * 16)
                                    : (const int4*)(lg + n * 16);
        int4 iA = ls4[0], iB = ls4[1], iC_ = ls4[2], iD = ls4[3];
        int idxs[16] = {iA.x, iA.y, iA.z, iA.w, iB.x, iB.y, iB.z, iB.w,
                        iC_.x, iC_.y, iC_.z, iC_.w, iD.x, iD.y, iD.z, iD.w};
        float ed = ed_s[n];
        float m = lrelu(es_s[n] + ed);
        #pragma unroll
        for (int k = 0; k < 16; k++) m = fmaxf(m, lrelu(es_s[idxs[k]] + ed));
        float* ap = alphaS + n * 17;
        float ssum = 0.f;
        #pragma unroll
        for (int k = 0; k < 16; k++) {
            float v = exp_neg(lrelu(es_s[idxs[k]] + ed) - m);
            ap[k] = v; ssum += v;
        }
        { float v = exp_neg(lrelu(es_s[n] + ed) - m); ap[16] = v; ssum += v; }
        float inv = 1.f / (ssum + 1e-16f);
        #pragma unroll
        for (int k = 0; k < 17; k++) ap[k] *= inv;
    }
    __syncthreads();
    // phase 3: quad-pair per task, int4 register indices
    for (int task = tid; task < NPG * G; task += blockDim.x) {
        int n = task / G, qg = task % G;
        int q0 = qg * 8;     // float offset of first quad
        const float* ap = alphaS + n * 17;
        const int4* ls4 = LSRC_SMEM ? (const int4*)(lsrcS + n * 16)
                                    : (const int4*)(lg + n * 16);
        int4 iA = ls4[0], iB = ls4[1], iC_ = ls4[2], iD = ls4[3];
        int idxs[16] = {iA.x, iA.y, iA.z, iA.w, iB.x, iB.y, iB.z, iB.w,
                        iC_.x, iC_.y, iC_.z, iC_.w, iD.x, iD.y, iD.z, iD.w};
        float4 acc0, acc1;
        {
            float a = ap[16];
            const float* tn = tile + n * C + q0;
            float4 v0 = *(const float4*)&tn[0];
            float4 v1 = *(const float4*)&tn[4];
            acc0.x = a * v0.x; acc0.y = a * v0.y; acc0.z = a * v0.z; acc0.w = a * v0.w;
            acc1.x = a * v1.x; acc1.y = a * v1.y; acc1.z = a * v1.z; acc1.w = a * v1.w;
        }
        #pragma unroll
        for (int k = 0; k < 16; k++) {
            float a = ap[k];
            const float* tr = tile + idxs[k] * C + q0;
            float4 v0 = *(const float4*)&tr[0];
            float4 v1 = *(const float4*)&tr[4];
            acc0.x = fmaf(a, v0.x, acc0.x); acc0.y = fmaf(a, v0.y, acc0.y);
            acc0.z = fmaf(a, v0.z, acc0.z); acc0.w = fmaf(a, v0.w, acc0.w);
            acc1.x = fmaf(a, v1.x, acc1.x); acc1.y = fmaf(a, v1.y, acc1.y);
            acc1.z = fmaf(a, v1.z, acc1.z); acc1.w = fmaf(a, v1.w, acc1.w);
        }
        float* orow = Xout + (size_t)(base + n) * HC + h * C + q0;
        float4 o0, o1;
        o0.x = elu_f(acc0.x + bi_s[q0 + 0]); o0.y = elu_f(acc0.y + bi_s[q0 + 1]);
        o0.z = elu_f(acc0.z + bi_s[q0 + 2]); o0.w = elu_f(acc0.w + bi_s[q0 + 3]);
        o1.x = elu_f(acc1.x + bi_s[q0 + 4]); o1.y = elu_f(acc1.y + bi_s[q0 + 5]);
        o1.z = elu_f(acc1.z + bi_s[q0 + 6]); o1.w = elu_f(acc1.w + bi_s[q0 + 7]);
        *(float4*)&orow[0] = o0;
        *(float4*)&orow[4] = o1;
    }
}

// ---------------- fused layer 4: GEMM + GAT + pool ----------------
__global__ __launch_bounds__(1024, 1)
void l4_fused(const float* __restrict__ X, const float* __restrict__ W4,
              const float* __restrict__ as4, const float* __restrict__ ad4,
              const float* __restrict__ b4) {
    extern __shared__ float sm[];
    float* w4s    = sm;
    float* tile   = w4s + 1024;
    float* es_s   = tile + NPG * 8;
    float* ed_s   = es_s + NPG;
    float* alphaS = ed_s + NPG;
    int*   lsrcS  = (int*)(alphaS + NPG * 17);
    __shared__ float as_s[8], ad_s[8], bi_s[8];
    __shared__ float poolS[8];
    int tb = blockIdx.x;
    int b = tb % B_GR;
    int t = tb / B_GR;
    int base = t * N_NODES + b * NPG;
    int tid = threadIdx.x;
    if (tid < 8) { as_s[tid] = as4[tid]; ad_s[tid] = ad4[tid]; bi_s[tid] = b4[tid]; poolS[tid] = 0.f; }
    for (int i = tid; i < 1024; i += 1024) w4s[i] = W4[i];
    {
        const int* lg = g_lsrc + (size_t)b * NPG * 16;
        for (int i = tid; i < NPG * 4; i += 1024)
            ((int4*)lsrcS)[i] = ((const int4*)lg)[i];
    }
    __syncthreads();
    for (int n = tid; n < NPG; n += 1024) {
        const float4* xr = (const float4*)(X + (size_t)(base + n) * 128);
        float4 a0 = make_float4(0, 0, 0, 0), a1 = make_float4(0, 0, 0, 0);
        #pragma unroll 8
        for (int k4 = 0; k4 < 32; k4++) {
            float4 xv = xr[k4];
            float xsv[4] = {xv.x, xv.y, xv.z, xv.w};
            #pragma unroll
            for (int kk = 0; kk < 4; kk++) {
                float xs = xsv[kk];
                float4 w0 = *(const float4*)&w4s[(k4 * 4 + kk) * 8];
                float4 w1 = *(const float4*)&w4s[(k4 * 4 + kk) * 8 + 4];
                a0.x = fmaf(xs, w0.x, a0.x); a0.y = fmaf(xs, w0.y, a0.y);
                a0.z = fmaf(xs, w0.z, a0.z); a0.w = fmaf(xs, w0.w, a0.w);
                a1.x = fmaf(xs, w1.x, a1.x); a1.y = fmaf(xs, w1.y, a1.y);
                a1.z = fmaf(xs, w1.z, a1.z); a1.w = fmaf(xs, w1.w, a1.w);
            }
        }
        *(float4*)&tile[n * 8] = a0;
        *(float4*)&tile[n * 8 + 4] = a1;
    }
    __syncthreads();
    for (int n = tid; n < NPG; n += 1024) {
        const float* tn = tile + n * 8;
        float se = 0.f, de = 0.f;
        #pragma unroll
        for (int q = 0; q < 2; q++) {
            float4 v = *(const float4*)&tn[q * 4];
            float4 a = *(const float4*)&as_s[q * 4];
            float4 d = *(const float4*)&ad_s[q * 4];
            se = fmaf(v.x, a.x, fmaf(v.y, a.y, fmaf(v.z, a.z, fmaf(v.w, a.w, se))));
            de = fmaf(v.x, d.x, fmaf(v.y, d.y, fmaf(v.z, d.z, fmaf(v.w, d.w, de))));
        }
        es_s[n] = se; ed_s[n] = de;
    }
    __syncthreads();
    for (int n = tid; n < NPG; n += 1024) {
        const int4* ls4 = (const int4*)(lsrcS + n * 16);
        int4 iA = ls4[0], iB = ls4[1], iC_ = ls4[2], iD = ls4[3];
        int idxs[16] = {iA.x, iA.y, iA.z, iA.w, iB.x, iB.y, iB.z, iB.w,
                        iC_.x, iC_.y, iC_.z, iC_.w, iD.x, iD.y, iD.z, iD.w};
        float ed = ed_s[n];
        float m = lrelu(es_s[n] + ed);
        #pragma unroll
        for (int k = 0; k < 16; k++) m = fmaxf(m, lrelu(es_s[idxs[k]] + ed));
        float* ap = alphaS + n * 17;
        float ssum = 0.f;
        #pragma unroll
        for (int k = 0; k < 16; k++) {
            float v = exp_neg(lrelu(es_s[idxs[k]] + ed) - m);
            ap[k] = v; ssum += v;
        }
        { float v = exp_neg(lrelu(es_s[n] + ed) - m); ap[16] = v; ssum += v; }
        float inv = 1.f / (ssum + 1e-16f);
        #pragma unroll
        for (int k = 0; k < 17; k++) ap[k] *= inv;
    }
    __syncthreads();
    // phase 3: one node per task (both quads), int4 indices
    float psum[8] = {};
    for (int n = tid; n < NPG; n += 1024) {
        const float* ap = alphaS + n * 17;
        const int4* ls4 = (const int4*)(lsrcS + n * 16);
        int4 iA = ls4[0], iB = ls4[1], iC_ = ls4[2], iD = ls4[3];
        int idxs[16] = {iA.x, iA.y, iA.z, iA.w, iB.x, iB.y, iB.z, iB.w,
                        iC_.x, iC_.y, iC_.z, iC_.w, iD.x, iD.y, iD.z, iD.w};
        float4 acc0, acc1;
        {
            float a = ap[16];
            float4 v0 = *(const float4*)&tile[n * 8];
            float4 v1 = *(const float4*)&tile[n * 8 + 4];
            acc0.x = a * v0.x; acc0.y = a * v0.y; acc0.z = a * v0.z; acc0.w = a * v0.w;
            acc1.x = a * v1.x; acc1.y = a * v1.y; acc1.z = a * v1.z; acc1.w = a * v1.w;
        }
        #pragma unroll
        for (int k = 0; k < 16; k++) {
            float a = ap[k];
            const float* tr = tile + idxs[k] * 8;
            float4 v0 = *(const float4*)&tr[0];
            float4 v1 = *(const float4*)&tr[4];
            acc0.x = fmaf(a, v0.x, acc0.x); acc0.y = fmaf(a, v0.y, acc0.y);
            acc0.z = fmaf(a, v0.z, acc0.z); acc0.w = fmaf(a, v0.w, acc0.w);
            acc1.x = fmaf(a, v1.x, acc1.x); acc1.y = fmaf(a, v1.y, acc1.y);
            acc1.z = fmaf(a, v1.z, acc1.z); acc1.w = fmaf(a, v1.w, acc1.w);
        }
        psum[0] += elu_f(acc0.x + bi_s[0]); psum[1] += elu_f(acc0.y + bi_s[1]);
        psum[2] += elu_f(acc0.z + bi_s[2]); psum[3] += elu_f(acc0.w + bi_s[3]);
        psum[4] += elu_f(acc1.x + bi_s[4]); psum[5] += elu_f(acc1.y + bi_s[5]);
        psum[6] += elu_f(acc1.z + bi_s[6]); psum[7] += elu_f(acc1.w + bi_s[7]);
    }
    #pragma unroll
    for (int f = 0; f < 8; f++) {
        float v = psum[f];
        #pragma unroll
        for (int off = 16; off > 0; off >>= 1)
            v += __shfl_down_sync(0xffffffff, v, off);
        if ((tid & 31) == 0 && v != 0.f) atomicAdd(&poolS[f], v);
    }
    __syncthreads();
    if (tid < 8) g_emb[tb * 8 + tid] = poolS[tid] * (1.0f / (float)NPG);
}

// ---------------- LSTM + FC ----------------
__device__ __forceinline__ float sigmoidf(float x) { return 1.f / (1.f + expf(-x)); }

__global__ void lstm_fc(const float* __restrict__ w_ih, const float* __restrict__ w_hh,
                        const float* __restrict__ b_ih, const float* __restrict__ b_hh,
                        const float* __restrict__ w_fc, const float* __restrict__ b_fc,
                        float* __restrict__ out) {
    __shared__ float h[8][128], c[8][128], g[8][512], xs[8][8];
    int tid = threadIdx.x;
    for (int i = tid; i < 8 * 128; i += 1024) { ((float*)h)[i] = 0.f; ((float*)c)[i] = 0.f; }
    __syncthreads();
    for (int t = 0; t < T_STEPS; t++) {
        if (tid < 64) xs[tid >> 3][tid & 7] = g_emb[t * 64 + tid];
        __syncthreads();
        #pragma unroll
        for (int task = tid; task < 4096; task += 1024) {
            int b = task >> 9, row = task & 511;
            float acc = b_ih[row] + b_hh[row];
            const float* wi = w_ih + row * 8;
            #pragma unroll
            for (int k = 0; k < 8; k++) acc += xs[b][k] * wi[k];
            const float4* wh = (const float4*)(w_hh + row * 128);
            const float4* hb = (const float4*)h[b];
            #pragma unroll 8
            for (int jj = 0; jj < 32; jj++) {
                float4 w4 = wh[jj], h4 = hb[jj];
                acc = fmaf(w4.x, h4.x, acc); acc = fmaf(w4.y, h4.y, acc);
                acc = fmaf(w4.z, h4.z, acc); acc = fmaf(w4.w, h4.w, acc);
            }
            g[b][row] = acc;
        }
        __syncthreads();
        if (tid < 1024) {
            int b = tid >> 7, u = tid & 127;
            float ig = sigmoidf(g[b][u]);
            float fg = sigmoidf(g[b][128 + u]);
            float gg = tanhf(g[b][256 + u]);
            float og = sigmoidf(g[b][384 + u]);
            float cn = fg * c[b][u] + ig * gg;
            c[b][u] = cn;
            h[b][u] = og * tanhf(cn);
        }
        __syncthreads();
    }
    if (tid < 16) {
        int b = tid >> 1, o = tid & 1;
        float acc = b_fc[o];
        const float* w = w_fc + o * 128;
        #pragma unroll 8
        for (int jj = 0; jj < 128; jj++) acc += h[b][jj] * w[jj];
        out[b * 2 + o] = acc;
    }
}

// ---------------- host launch ----------------
extern "C" void kernel_launch(void* const* d_in, const int* in_sizes, int n_in,
                              void* d_out, int out_size) {
    const float *x_seq = 0, *W1 = 0, *as1 = 0, *ad1 = 0, *b1 = 0;
    const float *W2 = 0, *as2 = 0, *ad2 = 0, *b2 = 0;
    const float *W3 = 0, *as3 = 0, *ad3 = 0, *b3 = 0;
    const float *W4 = 0, *as4 = 0, *ad4 = 0, *b4 = 0;
    const float *w_ih = 0, *w_hh = 0, *b_ih = 0, *b_hh = 0, *w_fc = 0, *b_fc = 0;
    const int *edge = 0;
    int c1024 = 0, c512 = 0, c256 = 0, c128 = 0, c8 = 0;
    for (int i = 0; i < n_in; i++) {
        const float* p = (const float*)d_in[i];
        switch (in_sizes[i]) {
            case 172800: x_seq = p; break;
            case 276480: edge = (const int*)p; break;
            case 8640:   break;
            case 131072: W2 = p; break;
            case 65536:  w_hh = p; break;
            case 32768:  W3 = p; break;
            case 4096:   w_ih = p; break;
            case 1024:   { if (c1024++ == 0) W1 = p; else W4 = p; } break;
            case 512: { int k = c512++;
                if (k == 0) as1 = p; else if (k == 1) ad1 = p; else if (k == 2) b1 = p;
                else if (k == 3) b_ih = p; else b_hh = p; } break;
            case 256: { int k = c256++;
                if (k == 0) as2 = p; else if (k == 1) ad2 = p; else if (k == 2) b2 = p;
                else w_fc = p; } break;
            case 128: { int k = c128++;
                if (k == 0) as3 = p; else if (k == 1) ad3 = p; else b3 = p; } break;
            case 8: { int k = c8++;
                if (k == 0) as4 = p; else if (k == 1) ad4 = p; else b4 = p; } break;
            case 2: b_fc = p; break;
            default: break;
        }
    }
    const int* src = edge;

    float *bufA, *bufB;
    __nv_bfloat16 *W2hi, *W2lo, *W3hi, *W3lo;
    cudaGetSymbolAddress((void**)&bufA, g_bufA);
    cudaGetSymbolAddress((void**)&bufB, g_bufB);
    cudaGetSymbolAddress((void**)&W2hi, g_W2hi);
    cudaGetSymbolAddress((void**)&W2lo, g_W2lo);
    cudaGetSymbolAddress((void**)&W3hi, g_W3hi);
    cudaGetSymbolAddress((void**)&W3lo, g_W3lo);

    const int SM_F32 = (NPG * 32 + NPG * 2 + NPG * 17) * 4;
    const int SM_F16 = (NPG * 16 + NPG * 2 + NPG * 17 + NPG * 16) * 4;
    const int SM_L4  = (1024 + NPG * 8 + NPG * 2 + NPG * 17 + NPG * 16) * 4;
    cudaFuncSetAttribute(fused_gat<8, 32, false>, cudaFuncAttributeMaxDynamicSharedMemorySize, SM_F32);
    cudaFuncSetAttribute(fused_gat<8, 16, true>,  cudaFuncAttributeMaxDynamicSharedMemorySize, SM_F16);
    cudaFuncSetAttribute(l4_fused, cudaFuncAttributeMaxDynamicSharedMemorySize, SM_L4);

    // 1: merged setup
    setup_all<<<1181, 256>>>(src, W2, W3, W1, as1, ad1);
    // 2: layer-1 z
    l1_z<<<640, 256>>>(x_seq);
    // 3: L2 GEMM
    l1gemm_bf16<<<dim3(2, TN / 128), 512>>>(W1, b1, W2hi, W2lo, bufA);
    // 4 (PROFILED): GAT layer 2 with new phase-3
    fused_gat<8, 32, false><<<T_STEPS * B_GR * 8, 1024, SM_F32>>>(bufA, as2, ad2, b2, bufB);
    // 5: L3 GEMM
    gemm3_bf16<<<dim3(1, TN / 128), 512>>>(bufB, W3hi, W3lo, bufA);
    // 6: GAT layer 3
    fused_gat<8, 16, true><<<T_STEPS * B_GR * 8, 1024, SM_F16>>>(bufA, as3, ad3, b3, bufB);
    // 7: fused layer 4
    l4_fused<<<T_STEPS * B_GR, 1024, SM_L4>>>(bufB, W4, as4, ad4, b4);
    // 8: LSTM + FC
    lstm_fc<<<1, 1024>>>(w_ih, w_hh, b_ih, b_hh, w_fc, b_fc, (float*)d_out);
}

// round 14
// speedup vs baseline: 1.0486x; 1.0486x over previous
#include <cuda_runtime.h>
#include <cuda_bf16.h>
#include <math.h>

#define T_STEPS 10
#define B_GR    8
#define NPG     1080
#define N_NODES 8640
#define TN      86400
#define DEG     16

// ---------------- scratch ----------------
__device__ float g_bufA[(size_t)TN * 256];
__device__ float g_bufB[(size_t)TN * 256];
__device__ float g_z[TN * 16];
__device__ __nv_bfloat16 g_W2hi[512 * 256], g_W2lo[512 * 256];
__device__ __nv_bfloat16 g_W3hi[256 * 128], g_W3lo[256 * 128];
__device__ float g_emb[T_STEPS * B_GR * 8];
__device__ float g_uv[32];
__device__ int   g_lsrc[N_NODES * 16];

__device__ __forceinline__ void split_bf16(float x, __nv_bfloat16& h, __nv_bfloat16& l) {
    h = __float2bfloat16_rn(x);
    l = __float2bfloat16_rn(x - __bfloat162float(h));
}

// ---------------- fast exp for x <= 0 ----------------
__device__ __forceinline__ float exp_neg(float x) {
    x = fmaxf(x, -87.0f);
    const float L2E = 1.4426950408889634f;
    float z = fmaf(x, L2E, 12582912.0f);
    int   ei = __float_as_int(z);
    float n = z - 12582912.0f;
    float f = fmaf(x, L2E, -n);
    float r = fmaf(1.5403530e-4f, f, 1.3333558e-3f);
    r = fmaf(r, f, 9.6181291e-3f);
    r = fmaf(r, f, 5.5504109e-2f);
    r = fmaf(r, f, 2.4022651e-1f);
    r = fmaf(r, f, 6.9314718e-1f);
    r = fmaf(r, f, 1.0f);
    float s = __int_as_float((ei + 127) << 23);
    return r * s;
}
__device__ __forceinline__ float elu_f(float v) { return v > 0.f ? v : exp_neg(v) - 1.f; }
__device__ __forceinline__ float lrelu(float e) { return e >= 0.f ? e : 0.2f * e; }

// ---------------- setup ----------------
__global__ void setup_lsrc(const int* __restrict__ src) {
    int i = blockIdx.x * 256 + threadIdx.x;
    int b = i / (NPG * 16);
    g_lsrc[i] = src[i] - b * NPG;
}

__global__ void setup_w(const float* __restrict__ W2, const float* __restrict__ W3,
                        const float* __restrict__ W1, const float* __restrict__ as1,
                        const float* __restrict__ ad1) {
    int bid = blockIdx.x, tid = threadIdx.x;
    if (bid < 512) {
        int i = bid * 256 + tid;
        split_bf16(W2[i], g_W2hi[i], g_W2lo[i]);
    } else if (bid < 640) {
        int i = (bid - 512) * 256 + tid;
        split_bf16(W3[i], g_W3hi[i], g_W3lo[i]);
    } else if (tid < 32) {
        int d = tid >> 4, h = (tid >> 1) & 7, f = tid & 1;
        const float* a = d ? ad1 : as1;
        float s = 0.f;
        #pragma unroll
        for (int c = 0; c < 64; c++) s += W1[f * 512 + h * 64 + c] * a[h * 64 + c];
        g_uv[tid] = s;
    }
}

// ---------------- layer 1: x -> z[TN,16] ----------------
__global__ __launch_bounds__(256)
void l1_z(const float* __restrict__ x) {
    __shared__ float xs[NPG * 2];
    __shared__ float es_s[NPG * 8];
    __shared__ float uvS[32];
    int blk = blockIdx.x;
    int chunk = blk & 7;
    int tb = blk >> 3;
    int b = tb & 7, t = tb >> 3;
    int base = t * N_NODES + b * NPG;
    int tid = threadIdx.x;
    if (tid < 32) uvS[tid] = g_uv[tid];
    for (int i = tid; i < NPG * 2; i += 256) xs[i] = x[(size_t)base * 2 + i];
    __syncthreads();
    for (int task = tid; task < NPG * 8; task += 256) {
        int n = task >> 3, h = task & 7;
        es_s[task] = fmaf(xs[n * 2], uvS[h * 2], xs[n * 2 + 1] * uvS[h * 2 + 1]);
    }
    __syncthreads();
    int n0 = chunk * 135;
    for (int task = tid; task < 135 * 8; task += 256) {
        int nl = task >> 3, h = task & 7;
        int n = n0 + nl;
        const int4* ls4 = (const int4*)(g_lsrc + ((size_t)b * NPG + n) * 16);
        int4 iA = ls4[0], iB = ls4[1], iC = ls4[2], iD = ls4[3];
        int idxs[16] = {iA.x, iA.y, iA.z, iA.w, iB.x, iB.y, iB.z, iB.w,
                        iC.x, iC.y, iC.z, iC.w, iD.x, iD.y, iD.z, iD.w};
        float ed = fmaf(xs[n * 2], uvS[16 + h * 2], xs[n * 2 + 1] * uvS[17 + h * 2]);
        float ev[17];
        float m = -1e30f;
        #pragma unroll
        for (int k = 0; k < 16; k++) {
            float e = lrelu(es_s[idxs[k] * 8 + h] + ed);
            ev[k] = e; m = fmaxf(m, e);
        }
        { float e = lrelu(es_s[n * 8 + h] + ed); ev[16] = e; m = fmaxf(m, e); }
        float ssum = 0.f;
        #pragma unroll
        for (int k = 0; k < 17; k++) { float v = exp_neg(ev[k] - m); ev[k] = v; ssum += v; }
        float inv = 1.f / (ssum + 1e-16f);
        float z0 = 0.f, z1 = 0.f;
        #pragma unroll
        for (int k = 0; k < 16; k++) {
            float a = ev[k] * inv;
            z0 = fmaf(a, xs[idxs[k] * 2], z0);
            z1 = fmaf(a, xs[idxs[k] * 2 + 1], z1);
        }
        {
            float a = ev[16] * inv;
            z0 = fmaf(a, xs[n * 2], z0);
            z1 = fmaf(a, xs[n * 2 + 1], z1);
        }
        *(float2*)&g_z[(size_t)(base + n) * 16 + h * 2] = make_float2(z0, z1);
    }
}

// ---------------- GEMM macros ----------------
#define MMA_BF16(d, a, b0, b1) \
    asm volatile("mma.sync.aligned.m16n8k16.row.col.f32.bf16.bf16.f32 " \
        "{%0,%1,%2,%3}, {%4,%5,%6,%7}, {%8,%9}, {%0,%1,%2,%3};" \
        : "+f"(d[0]), "+f"(d[1]), "+f"(d[2]), "+f"(d[3]) \
        : "r"(a[0]), "r"(a[1]), "r"(a[2]), "r"(a[3]), "r"(b0), "r"(b1))

#define LDMX4(r, addr) \
    asm volatile("ldmatrix.sync.aligned.m8n8.x4.shared.b16 {%0,%1,%2,%3}, [%4];" \
        : "=r"(r[0]), "=r"(r[1]), "=r"(r[2]), "=r"(r[3]) : "r"(addr))

#define LDMX4T(r, addr) \
    asm volatile("ldmatrix.sync.aligned.m8n8.x4.trans.shared.b16 {%0,%1,%2,%3}, [%4];" \
        : "=r"(r[0]), "=r"(r[1]), "=r"(r[2]), "=r"(r[3]) : "r"(addr))

#define CP16(dst, src) \
    asm volatile("cp.async.cg.shared.global [%0], [%1], 16;" :: "r"(dst), "l"(src))
#define CP_COMMIT asm volatile("cp.async.commit_group;")
#define CP_WAIT1  asm volatile("cp.async.wait_group 1;")
#define CP_WAIT0  asm volatile("cp.async.wait_group 0;")

#define ASTR 24
#define BSTR2 136

struct alignas(8) US4 { unsigned short v[4]; };

// ---------------- L2 GEMM with A generated from z (single-buffer sA) ----------------
__global__ __launch_bounds__(512)
void l1gemm_bf16(const float* __restrict__ W1, const float* __restrict__ b1,
                 const __nv_bfloat16* __restrict__ Whi, const __nv_bfloat16* __restrict__ Wlo,
                 float* __restrict__ C) {
    const int Nc = 256;
    __shared__ alignas(16) unsigned short sA[2][128 * ASTR];
    __shared__ alignas(16) unsigned short sB[3][2][16 * BSTR2];
    __shared__ float zs[128][16];
    __shared__ float W1s[1024], b1s[512];
    const int tid = threadIdx.x;
    const int lane = tid & 31, wid = tid >> 5;
    const int warpM = wid & 3, warpN = wid >> 2;
    const int rb = blockIdx.y * 128, cb = blockIdx.x * 128;
    const int hl = tid >> 8;
    const int j = tid & 255;
    const int brow = j >> 4, bcol = (j & 15) * 8;
    const __nv_bfloat16* bptr = (hl ? Wlo : Whi) + (size_t)brow * Nc + cb + bcol;
    unsigned sb_dst[3];
    #pragma unroll
    for (int s = 0; s < 3; s++)
        sb_dst[s] = (unsigned)__cvta_generic_to_shared(&sB[s][hl][brow * BSTR2 + bcol]);
    {
        int row = tid >> 2, q = tid & 3;
        *(float4*)&zs[row][q * 4] = *(const float4*)(g_z + (size_t)(rb + row) * 16 + q * 4);
    }
    for (int i = tid; i < 1024; i += 512) W1s[i] = W1[i];
    if (tid < 512) b1s[tid] = b1[tid];
    CP16(sb_dst[0], bptr);
    CP_COMMIT;
    CP16(sb_dst[1], bptr + (size_t)16 * Nc);
    CP_COMMIT;
    __syncthreads();

    const int arow = tid >> 2, ac0 = (tid & 3) * 4;
    const int a_r = (lane & 15);
    const int a_c = (lane >> 4) * 8;
    const int b_k = (lane & 7) + (lane & 8);
    const int b_n = (lane & 16) >> 1;
    float acc[2][4][4] = {};
    const int nk = 32;

    for (int ck = 0; ck < nk; ck++) {
        {
            int h = ck >> 2;
            float z0 = zs[arow][h * 2], z1 = zs[arow][h * 2 + 1];
            US4 hv, lv;
            #pragma unroll
            for (int i = 0; i < 4; i++) {
                int k = ck * 16 + ac0 + i;
                float v = elu_f(fmaf(z0, W1s[k], fmaf(z1, W1s[512 + k], b1s[k])));
                __nv_bfloat16 bh, bl;
                split_bf16(v, bh, bl);
                hv.v[i] = *(unsigned short*)&bh;
                lv.v[i] = *(unsigned short*)&bl;
            }
            *(US4*)&sA[0][arow * ASTR + ac0] = hv;
            *(US4*)&sA[1][arow * ASTR + ac0] = lv;
        }
        if (ck + 1 < nk) { CP_WAIT1; } else { CP_WAIT0; }
        __syncthreads();
        if (ck + 2 < nk) {
            int buf = (ck + 2) % 3;
            CP16(sb_dst[buf], bptr + (size_t)((ck + 2) * 16) * Nc);
            CP_COMMIT;
        }
        int p = ck % 3;
        unsigned ah[2][4], al[2][4];
        #pragma unroll
        for (int ma = 0; ma < 2; ma++) {
            int r = warpM * 32 + ma * 16 + a_r;
            unsigned adh = (unsigned)__cvta_generic_to_shared(&sA[0][r * ASTR + a_c]);
            unsigned adl = (unsigned)__cvta_generic_to_shared(&sA[1][r * ASTR + a_c]);
            LDMX4(ah[ma], adh);
            LDMX4(al[ma], adl);
        }
        unsigned bh[4][2], bl[4][2];
        #pragma unroll
        for (int g = 0; g < 2; g++) {
            int n0 = warpN * 32 + g * 16 + b_n;
            unsigned adh = (unsigned)__cvta_generic_to_shared(&sB[p][0][b_k * BSTR2 + n0]);
            unsigned adl = (unsigned)__cvta_generic_to_shared(&sB[p][1][b_k * BSTR2 + n0]);
            unsigned th[4], tl[4];
            LDMX4T(th, adh);
            LDMX4T(tl, adl);
            bh[g * 2][0] = th[0]; bh[g * 2][1] = th[1];
            bh[g * 2 + 1][0] = th[2]; bh[g * 2 + 1][1] = th[3];
            bl[g * 2][0] = tl[0]; bl[g * 2][1] = tl[1];
            bl[g * 2 + 1][0] = tl[2]; bl[g * 2 + 1][1] = tl[3];
        }
        #pragma unroll
        for (int ma = 0; ma < 2; ma++)
            #pragma unroll
            for (int na = 0; na < 4; na++) {
                MMA_BF16(acc[ma][na], ah[ma], bh[na][0], bh[na][1]);
                MMA_BF16(acc[ma][na], ah[ma], bl[na][0], bl[na][1]);
                MMA_BF16(acc[ma][na], al[ma], bh[na][0], bh[na][1]);
            }
        __syncthreads();
    }
    #pragma unroll
    for (int ma = 0; ma < 2; ma++)
        #pragma unroll
        for (int na = 0; na < 4; na++) {
            int r0 = rb + warpM * 32 + ma * 16 + (lane >> 2);
            int c = cb + warpN * 32 + na * 8 + (lane & 3) * 2;
            *(float2*)(C + (size_t)r0 * Nc + c)       = make_float2(acc[ma][na][0], acc[ma][na][1]);
            *(float2*)(C + (size_t)(r0 + 8) * Nc + c) = make_float2(acc[ma][na][2], acc[ma][na][3]);
        }
}

// ---------------- L3 GEMM: fp32 A split during staging ----------------
__global__ __launch_bounds__(512)
void gemm3_bf16(const float* __restrict__ A,
                const __nv_bfloat16* __restrict__ Whi, const __nv_bfloat16* __restrict__ Wlo,
                float* __restrict__ C) {
    const int K = 256, Nc = 128;
    __shared__ alignas(16) unsigned short sA[2][128 * ASTR];
    __shared__ alignas(16) unsigned short sB[3][2][16 * BSTR2];
    const int tid = threadIdx.x;
    const int lane = tid & 31, wid = tid >> 5;
    const int warpM = wid & 3, warpN = wid >> 2;
    const int rb = blockIdx.y * 128;
    const int hl = tid >> 8;
    const int j = tid & 255;
    const int brow = j >> 4, bcol = (j & 15) * 8;
    const __nv_bfloat16* bptr = (hl ? Wlo : Whi) + (size_t)brow * Nc + bcol;
    unsigned sb_dst[3];
    #pragma unroll
    for (int s = 0; s < 3; s++)
        sb_dst[s] = (unsigned)__cvta_generic_to_shared(&sB[s][hl][brow * BSTR2 + bcol]);
    const int arow = tid >> 2, ac0 = (tid & 3) * 4;
    const float* aptr = A + (size_t)(rb + arow) * K + ac0;
    CP16(sb_dst[0], bptr);
    CP_COMMIT;
    CP16(sb_dst[1], bptr + (size_t)16 * Nc);
    CP_COMMIT;
    float4 areg = *(const float4*)(aptr);
    const int a_r = (lane & 15);
    const int a_c = (lane >> 4) * 8;
    const int b_k = (lane & 7) + (lane & 8);
    const int b_n = (lane & 16) >> 1;
    float acc[2][4][4] = {};
    const int nk = 16;

    for (int ck = 0; ck < nk; ck++) {
        {
            US4 hv, lv;
            float vals[4] = {areg.x, areg.y, areg.z, areg.w};
            #pragma unroll
            for (int i = 0; i < 4; i++) {
                __nv_bfloat16 bh, bl;
                split_bf16(vals[i], bh, bl);
                hv.v[i] = *(unsigned short*)&bh;
                lv.v[i] = *(unsigned short*)&bl;
            }
            *(US4*)&sA[0][arow * ASTR + ac0] = hv;
            *(US4*)&sA[1][arow * ASTR + ac0] = lv;
        }
        if (ck + 1 < nk) { CP_WAIT1; } else { CP_WAIT0; }
        __syncthreads();
        if (ck + 1 < nk) areg = *(const float4*)(aptr + (ck + 1) * 16);
        if (ck + 2 < nk) {
            int buf = (ck + 2) % 3;
            CP16(sb_dst[buf], bptr + (size_t)((ck + 2) * 16) * Nc);
            CP_COMMIT;
        }
        int p = ck % 3;
        unsigned ah[2][4], al[2][4];
        #pragma unroll
        for (int ma = 0; ma < 2; ma++) {
            int r = warpM * 32 + ma * 16 + a_r;
            unsigned adh = (unsigned)__cvta_generic_to_shared(&sA[0][r * ASTR + a_c]);
            unsigned adl = (unsigned)__cvta_generic_to_shared(&sA[1][r * ASTR + a_c]);
            LDMX4(ah[ma], adh);
            LDMX4(al[ma], adl);
        }
        unsigned bh[4][2], bl[4][2];
        #pragma unroll
        for (int g = 0; g < 2; g++) {
            int n0 = warpN * 32 + g * 16 + b_n;
            unsigned adh = (unsigned)__cvta_generic_to_shared(&sB[p][0][b_k * BSTR2 + n0]);
            unsigned adl = (unsigned)__cvta_generic_to_shared(&sB[p][1][b_k * BSTR2 + n0]);
            unsigned th[4], tl[4];
            LDMX4T(th, adh);
            LDMX4T(tl, adl);
            bh[g * 2][0] = th[0]; bh[g * 2][1] = th[1];
            bh[g * 2 + 1][0] = th[2]; bh[g * 2 + 1][1] = th[3];
            bl[g * 2][0] = tl[0]; bl[g * 2][1] = tl[1];
            bl[g * 2 + 1][0] = tl[2]; bl[g * 2 + 1][1] = tl[3];
        }
        #pragma unroll
        for (int ma = 0; ma < 2; ma++)
            #pragma unroll
            for (int na = 0; na < 4; na++) {
                MMA_BF16(acc[ma][na], ah[ma], bh[na][0], bh[na][1]);
                MMA_BF16(acc[ma][na], ah[ma], bl[na][0], bl[na][1]);
                MMA_BF16(acc[ma][na], al[ma], bh[na][0], bh[na][1]);
            }
        __syncthreads();
    }
    #pragma unroll
    for (int ma = 0; ma < 2; ma++)
        #pragma unroll
        for (int na = 0; na < 4; na++) {
            int r0 = rb + warpM * 32 + ma * 16 + (lane >> 2);
            int c = warpN * 32 + na * 8 + (lane & 3) * 2;
            *(float2*)(C + (size_t)r0 * Nc + c)       = make_float2(acc[ma][na][0], acc[ma][na][1]);
            *(float2*)(C + (size_t)(r0 + 8) * Nc + c) = make_float2(acc[ma][na][2], acc[ma][na][3]);
        }
}

// ---------------- fully fused GAT (R12 task mapping; int4 idx hoist in phase 3) ----------------
template<int H, int C, bool LSRC_SMEM>
__global__ __launch_bounds__(1024, 1)
void fused_gat(const float* __restrict__ Y, const float* __restrict__ as_,
               const float* __restrict__ ad_, const float* __restrict__ bias,
               float* __restrict__ Xout) {
    extern __shared__ float sm[];
    constexpr int HC = H * C;
    constexpr int Q = C / 4;
    float* tile   = sm;
    float* es_s   = tile + NPG * C;
    float* ed_s   = es_s + NPG;
    float* alphaS = ed_s + NPG;
    int*   lsrcS  = (int*)(alphaS + NPG * 17);
    __shared__ float as_s[C], ad_s[C], bi_s[C];
    int blk = blockIdx.x;
    int h = blk % H;
    int tb = blk / H;
    int b = tb % B_GR;
    int t = tb / B_GR;
    int base = t * N_NODES + b * NPG;
    int tid = threadIdx.x;
    const int* lg = g_lsrc + (size_t)b * NPG * 16;
    if (tid < C) { as_s[tid] = as_[h * C + tid]; ad_s[tid] = ad_[h * C + tid]; bi_s[tid] = bias[h * C + tid]; }
    for (int i = tid; i < NPG * Q; i += blockDim.x) {
        int n = i / Q, q = i % Q;
        *(float4*)&tile[n * C + q * 4] =
            *(const float4*)(Y + (size_t)(base + n) * HC + h * C + q * 4);
    }
    if (LSRC_SMEM) {
        for (int i = tid; i < NPG * 4; i += blockDim.x)
            ((int4*)lsrcS)[i] = ((const int4*)lg)[i];
    }
    __syncthreads();
    // phase 1: es/ed
    for (int n = tid; n < NPG; n += blockDim.x) {
        const float* tn = tile + n * C;
        int rot1 = tid & (Q - 1);
        float se = 0.f, de = 0.f;
        #pragma unroll
        for (int jj = 0; jj < Q; jj++) {
            int q = (jj + rot1) & (Q - 1);
            float4 v = *(const float4*)&tn[q * 4];
            float4 a = *(const float4*)&as_s[q * 4];
            float4 d = *(const float4*)&ad_s[q * 4];
            se = fmaf(v.x, a.x, fmaf(v.y, a.y, fmaf(v.z, a.z, fmaf(v.w, a.w, se))));
            de = fmaf(v.x, d.x, fmaf(v.y, d.y, fmaf(v.z, d.z, fmaf(v.w, d.w, de))));
        }
        es_s[n] = se; ed_s[n] = de;
    }
    __syncthreads();
    // phase 2: softmax -> alphaS
    for (int n = tid; n < NPG; n += blockDim.x) {
        const int4* ls4 = LSRC_SMEM ? (const int4*)(lsrcS + n * 16)
                                    : (const int4*)(lg + n * 16);
        int4 iA = ls4[0], iB = ls4[1], iC_ = ls4[2], iD = ls4[3];
        int idxs[16] = {iA.x, iA.y, iA.z, iA.w, iB.x, iB.y, iB.z, iB.w,
                        iC_.x, iC_.y, iC_.z, iC_.w, iD.x, iD.y, iD.z, iD.w};
        float ed = ed_s[n];
        float m = lrelu(es_s[n] + ed);
        #pragma unroll
        for (int k = 0; k < 16; k++) m = fmaxf(m, lrelu(es_s[idxs[k]] + ed));
        float* ap = alphaS + n * 17;
        float ssum = 0.f;
        #pragma unroll
        for (int k = 0; k < 16; k++) {
            float v = exp_neg(lrelu(es_s[idxs[k]] + ed) - m);
            ap[k] = v; ssum += v;
        }
        { float v = exp_neg(lrelu(es_s[n] + ed) - m); ap[16] = v; ssum += v; }
        float inv = 1.f / (ssum + 1e-16f);
        #pragma unroll
        for (int k = 0; k < 17; k++) ap[k] *= inv;
    }
    __syncthreads();
    // phase 3: R12 (n,q) tasks; indices hoisted via int4
    for (int task = tid; task < NPG * Q; task += blockDim.x) {
        int n = task / Q, q = task % Q;
        const float* ap = alphaS + n * 17;
        const int4* ls4 = LSRC_SMEM ? (const int4*)(lsrcS + n * 16)
                                    : (const int4*)(lg + n * 16);
        int4 iA = ls4[0], iB = ls4[1], iC_ = ls4[2], iD = ls4[3];
        int idxs[16] = {iA.x, iA.y, iA.z, iA.w, iB.x, iB.y, iB.z, iB.w,
                        iC_.x, iC_.y, iC_.z, iC_.w, iD.x, iD.y, iD.z, iD.w};
        float4 acc = make_float4(0.f, 0.f, 0.f, 0.f);
        #pragma unroll
        for (int k = 0; k < 16; k++) {
            float a = ap[k];
            float4 v = *(const float4*)&tile[idxs[k] * C + q * 4];
            acc.x = fmaf(a, v.x, acc.x); acc.y = fmaf(a, v.y, acc.y);
            acc.z = fmaf(a, v.z, acc.z); acc.w = fmaf(a, v.w, acc.w);
        }
        {
            float a = ap[16];
            float4 v = *(const float4*)&tile[n * C + q * 4];
            acc.x = fmaf(a, v.x, acc.x); acc.y = fmaf(a, v.y, acc.y);
            acc.z = fmaf(a, v.z, acc.z); acc.w = fmaf(a, v.w, acc.w);
        }
        float4 o;
        o.x = elu_f(acc.x + bi_s[q * 4 + 0]);
        o.y = elu_f(acc.y + bi_s[q * 4 + 1]);
        o.z = elu_f(acc.z + bi_s[q * 4 + 2]);
        o.w = elu_f(acc.w + bi_s[q * 4 + 3]);
        *(float4*)(Xout + (size_t)(base + n) * HC + h * C + q * 4) = o;
    }
}

// ---------------- fused layer 4: GEMM + GAT + pool (R12 form) ----------------
__global__ __launch_bounds__(1024, 1)
void l4_fused(const float* __restrict__ X, const float* __restrict__ W4,
              const float* __restrict__ as4, const float* __restrict__ ad4,
              const float* __restrict__ b4) {
    extern __shared__ float sm[];
    float* w4s    = sm;
    float* tile   = w4s + 1024;
    float* es_s   = tile + NPG * 8;
    float* ed_s   = es_s + NPG;
    float* alphaS = ed_s + NPG;
    int*   lsrcS  = (int*)(alphaS + NPG * 17);
    __shared__ float as_s[8], ad_s[8], bi_s[8];
    __shared__ float poolS[8];
    int tb = blockIdx.x;
    int b = tb % B_GR;
    int t = tb / B_GR;
    int base = t * N_NODES + b * NPG;
    int tid = threadIdx.x;
    if (tid < 8) { as_s[tid] = as4[tid]; ad_s[tid] = ad4[tid]; bi_s[tid] = b4[tid]; poolS[tid] = 0.f; }
    for (int i = tid; i < 1024; i += 1024) w4s[i] = W4[i];
    {
        const int* lg = g_lsrc + (size_t)b * NPG * 16;
        for (int i = tid; i < NPG * 4; i += 1024)
            ((int4*)lsrcS)[i] = ((const int4*)lg)[i];
    }
    __syncthreads();
    for (int n = tid; n < NPG; n += 1024) {
        const float4* xr = (const float4*)(X + (size_t)(base + n) * 128);
        float4 a0 = make_float4(0, 0, 0, 0), a1 = make_float4(0, 0, 0, 0);
        #pragma unroll 8
        for (int k4 = 0; k4 < 32; k4++) {
            float4 xv = xr[k4];
            float xsv[4] = {xv.x, xv.y, xv.z, xv.w};
            #pragma unroll
            for (int kk = 0; kk < 4; kk++) {
                float xs = xsv[kk];
                float4 w0 = *(const float4*)&w4s[(k4 * 4 + kk) * 8];
                float4 w1 = *(const float4*)&w4s[(k4 * 4 + kk) * 8 + 4];
                a0.x = fmaf(xs, w0.x, a0.x); a0.y = fmaf(xs, w0.y, a0.y);
                a0.z = fmaf(xs, w0.z, a0.z); a0.w = fmaf(xs, w0.w, a0.w);
                a1.x = fmaf(xs, w1.x, a1.x); a1.y = fmaf(xs, w1.y, a1.y);
                a1.z = fmaf(xs, w1.z, a1.z); a1.w = fmaf(xs, w1.w, a1.w);
            }
        }
        *(float4*)&tile[n * 8] = a0;
        *(float4*)&tile[n * 8 + 4] = a1;
    }
    __syncthreads();
    for (int n = tid; n < NPG; n += 1024) {
        const float* tn = tile + n * 8;
        float se = 0.f, de = 0.f;
        #pragma unroll
        for (int q = 0; q < 2; q++) {
            float4 v = *(const float4*)&tn[q * 4];
            float4 a = *(const float4*)&as_s[q * 4];
            float4 d = *(const float4*)&ad_s[q * 4];
            se = fmaf(v.x, a.x, fmaf(v.y, a.y, fmaf(v.z, a.z, fmaf(v.w, a.w, se))));
            de = fmaf(v.x, d.x, fmaf(v.y, d.y, fmaf(v.z, d.z, fmaf(v.w, d.w, de))));
        }
        es_s[n] = se; ed_s[n] = de;
    }
    __syncthreads();
    for (int n = tid; n < NPG; n += 1024) {
        const int4* ls4 = (const int4*)(lsrcS + n * 16);
        int4 iA = ls4[0], iB = ls4[1], iC_ = ls4[2], iD = ls4[3];
        int idxs[16] = {iA.x, iA.y, iA.z, iA.w, iB.x, iB.y, iB.z, iB.w,
                        iC_.x, iC_.y, iC_.z, iC_.w, iD.x, iD.y, iD.z, iD.w};
        float ed = ed_s[n];
        float m = lrelu(es_s[n] + ed);
        #pragma unroll
        for (int k = 0; k < 16; k++) m = fmaxf(m, lrelu(es_s[idxs[k]] + ed));
        float* ap = alphaS + n * 17;
        float ssum = 0.f;
        #pragma unroll
        for (int k = 0; k < 16; k++) {
            float v = exp_neg(lrelu(es_s[idxs[k]] + ed) - m);
            ap[k] = v; ssum += v;
        }
        { float v = exp_neg(lrelu(es_s[n] + ed) - m); ap[16] = v; ssum += v; }
        float inv = 1.f / (ssum + 1e-16f);
        #pragma unroll
        for (int k = 0; k < 17; k++) ap[k] *= inv;
    }
    __syncthreads();
    float psum[8] = {};
    for (int task = tid; task < NPG * 2; task += 1024) {
        int n = task >> 1, q = task & 1;
        const float* ap = alphaS + n * 17;
        const int4* ls4 = (const int4*)(lsrcS + n * 16);
        int4 iA = ls4[0], iB = ls4[1], iC_ = ls4[2], iD = ls4[3];
        int idxs[16] = {iA.x, iA.y, iA.z, iA.w, iB.x, iB.y, iB.z, iB.w,
                        iC_.x, iC_.y, iC_.z, iC_.w, iD.x, iD.y, iD.z, iD.w};
        float4 acc = make_float4(0.f, 0.f, 0.f, 0.f);
        #pragma unroll
        for (int k = 0; k < 16; k++) {
            float a = ap[k];
            float4 v = *(const float4*)&tile[idxs[k] * 8 + q * 4];
            acc.x = fmaf(a, v.x, acc.x); acc.y = fmaf(a, v.y, acc.y);
            acc.z = fmaf(a, v.z, acc.z); acc.w = fmaf(a, v.w, acc.w);
        }
        {
            float a = ap[16];
            float4 v = *(const float4*)&tile[n * 8 + q * 4];
            acc.x = fmaf(a, v.x, acc.x); acc.y = fmaf(a, v.y, acc.y);
            acc.z = fmaf(a, v.z, acc.z); acc.w = fmaf(a, v.w, acc.w);
        }
        psum[q * 4 + 0] += elu_f(acc.x + bi_s[q * 4 + 0]);
        psum[q * 4 + 1] += elu_f(acc.y + bi_s[q * 4 + 1]);
        psum[q * 4 + 2] += elu_f(acc.z + bi_s[q * 4 + 2]);
        psum[q * 4 + 3] += elu_f(acc.w + bi_s[q * 4 + 3]);
    }
    #pragma unroll
    for (int f = 0; f < 8; f++) {
        float v = psum[f];
        #pragma unroll
        for (int off = 16; off > 0; off >>= 1)
            v += __shfl_down_sync(0xffffffff, v, off);
        if ((tid & 31) == 0 && v != 0.f) atomicAdd(&poolS[f], v);
    }
    __syncthreads();
    if (tid < 8) g_emb[tb * 8 + tid] = poolS[tid] * (1.0f / (float)NPG);
}

// ---------------- LSTM + FC ----------------
__device__ __forceinline__ float sigmoidf(float x) { return 1.f / (1.f + expf(-x)); }

__global__ void lstm_fc(const float* __restrict__ w_ih, const float* __restrict__ w_hh,
                        const float* __restrict__ b_ih, const float* __restrict__ b_hh,
                        const float* __restrict__ w_fc, const float* __restrict__ b_fc,
                        float* __restrict__ out) {
    __shared__ float h[8][128], c[8][128], g[8][512], xs[8][8];
    int tid = threadIdx.x;
    for (int i = tid; i < 8 * 128; i += 1024) { ((float*)h)[i] = 0.f; ((float*)c)[i] = 0.f; }
    __syncthreads();
    for (int t = 0; t < T_STEPS; t++) {
        if (tid < 64) xs[tid >> 3][tid & 7] = g_emb[t * 64 + tid];
        __syncthreads();
        #pragma unroll
        for (int task = tid; task < 4096; task += 1024) {
            int b = task >> 9, row = task & 511;
            float acc = b_ih[row] + b_hh[row];
            const float* wi = w_ih + row * 8;
            #pragma unroll
            for (int k = 0; k < 8; k++) acc += xs[b][k] * wi[k];
            const float4* wh = (const float4*)(w_hh + row * 128);
            const float4* hb = (const float4*)h[b];
            #pragma unroll 8
            for (int jj = 0; jj < 32; jj++) {
                float4 w4 = wh[jj], h4 = hb[jj];
                acc = fmaf(w4.x, h4.x, acc); acc = fmaf(w4.y, h4.y, acc);
                acc = fmaf(w4.z, h4.z, acc); acc = fmaf(w4.w, h4.w, acc);
            }
            g[b][row] = acc;
        }
        __syncthreads();
        if (tid < 1024) {
            int b = tid >> 7, u = tid & 127;
            float ig = sigmoidf(g[b][u]);
            float fg = sigmoidf(g[b][128 + u]);
            float gg = tanhf(g[b][256 + u]);
            float og = sigmoidf(g[b][384 + u]);
            float cn = fg * c[b][u] + ig * gg;
            c[b][u] = cn;
            h[b][u] = og * tanhf(cn);
        }
        __syncthreads();
    }
    if (tid < 16) {
        int b = tid >> 1, o = tid & 1;
        float acc = b_fc[o];
        const float* w = w_fc + o * 128;
        #pragma unroll 8
        for (int jj = 0; jj < 128; jj++) acc += h[b][jj] * w[jj];
        out[b * 2 + o] = acc;
    }
}

// ---------------- host launch ----------------
extern "C" void kernel_launch(void* const* d_in, const int* in_sizes, int n_in,
                              void* d_out, int out_size) {
    const float *x_seq = 0, *W1 = 0, *as1 = 0, *ad1 = 0, *b1 = 0;
    const float *W2 = 0, *as2 = 0, *ad2 = 0, *b2 = 0;
    const float *W3 = 0, *as3 = 0, *ad3 = 0, *b3 = 0;
    const float *W4 = 0, *as4 = 0, *ad4 = 0, *b4 = 0;
    const float *w_ih = 0, *w_hh = 0, *b_ih = 0, *b_hh = 0, *w_fc = 0, *b_fc = 0;
    const int *edge = 0;
    int c1024 = 0, c512 = 0, c256 = 0, c128 = 0, c8 = 0;
    for (int i = 0; i < n_in; i++) {
        const float* p = (const float*)d_in[i];
        switch (in_sizes[i]) {
            case 172800: x_seq = p; break;
            case 276480: edge = (const int*)p; break;
            case 8640:   break;
            case 131072: W2 = p; break;
            case 65536:  w_hh = p; break;
            case 32768:  W3 = p; break;
            case 4096:   w_ih = p; break;
            case 1024:   { if (c1024++ == 0) W1 = p; else W4 = p; } break;
            case 512: { int k = c512++;
                if (k == 0) as1 = p; else if (k == 1) ad1 = p; else if (k == 2) b1 = p;
                else if (k == 3) b_ih = p; else b_hh = p; } break;
            case 256: { int k = c256++;
                if (k == 0) as2 = p; else if (k == 1) ad2 = p; else if (k == 2) b2 = p;
                else w_fc = p; } break;
            case 128: { int k = c128++;
                if (k == 0) as3 = p; else if (k == 1) ad3 = p; else b3 = p; } break;
            case 8: { int k = c8++;
                if (k == 0) as4 = p; else if (k == 1) ad4 = p; else b4 = p; } break;
            case 2: b_fc = p; break;
            default: break;
        }
    }
    const int* src = edge;

    float *bufA, *bufB;
    __nv_bfloat16 *W2hi, *W2lo, *W3hi, *W3lo;
    cudaGetSymbolAddress((void**)&bufA, g_bufA);
    cudaGetSymbolAddress((void**)&bufB, g_bufB);
    cudaGetSymbolAddress((void**)&W2hi, g_W2hi);
    cudaGetSymbolAddress((void**)&W2lo, g_W2lo);
    cudaGetSymbolAddress((void**)&W3hi, g_W3hi);
    cudaGetSymbolAddress((void**)&W3lo, g_W3lo);

    const int SM_F32 = (NPG * 32 + NPG * 2 + NPG * 17) * 4;
    const int SM_F16 = (NPG * 16 + NPG * 2 + NPG * 17 + NPG * 16) * 4;
    const int SM_L4  = (1024 + NPG * 8 + NPG * 2 + NPG * 17 + NPG * 16) * 4;
    cudaFuncSetAttribute(fused_gat<8, 32, false>, cudaFuncAttributeMaxDynamicSharedMemorySize, SM_F32);
    cudaFuncSetAttribute(fused_gat<8, 16, true>,  cudaFuncAttributeMaxDynamicSharedMemorySize, SM_F16);
    cudaFuncSetAttribute(l4_fused, cudaFuncAttributeMaxDynamicSharedMemorySize, SM_L4);

    // 1: localize src
    setup_lsrc<<<540, 256>>>(src);
    // 2: W splits + uvec
    setup_w<<<641, 256>>>(W2, W3, W1, as1, ad1);
    // 3: layer-1 z
    l1_z<<<640, 256>>>(x_seq);
    // 4 (PROFILED): L2 GEMM
    l1gemm_bf16<<<dim3(2, TN / 128), 512>>>(W1, b1, W2hi, W2lo, bufA);
    // 5: GAT layer 2
    fused_gat<8, 32, false><<<T_STEPS * B_GR * 8, 1024, SM_F32>>>(bufA, as2, ad2, b2, bufB);
    // 6: L3 GEMM
    gemm3_bf16<<<dim3(1, TN / 128), 512>>>(bufB, W3hi, W3lo, bufA);
    // 7: GAT layer 3
    fused_gat<8, 16, true><<<T_STEPS * B_GR * 8, 1024, SM_F16>>>(bufA, as3, ad3, b3, bufB);
    // 8: fused layer 4
    l4_fused<<<T_STEPS * B_GR, 1024, SM_L4>>>(bufB, W4, as4, ad4, b4);
    // 9: LSTM + FC
    lstm_fc<<<1, 1024>>>(w_ih, w_hh, b_ih, b_hh, w_fc, b_fc, (float*)d_out);
}

// round 15
// speedup vs baseline: 1.9233x; 1.8343x over previous
#include <cuda_runtime.h>
#include <cuda_bf16.h>
#include <math.h>

#define T_STEPS 10
#define B_GR    8
#define NPG     1080
#define N_NODES 8640
#define TN      86400
#define DEG     16

// ---------------- scratch ----------------
__device__ float g_bufA[(size_t)TN * 256];
__device__ float g_bufB[(size_t)TN * 256];
__device__ float g_z[TN * 16];
__device__ __nv_bfloat16 g_W2hi[512 * 256], g_W2lo[512 * 256];
__device__ __nv_bfloat16 g_W3hi[256 * 128], g_W3lo[256 * 128];
__device__ float g_emb[T_STEPS * B_GR * 8];
__device__ float g_uv[32];
__device__ int   g_lsrc[N_NODES * 16];

__device__ __forceinline__ void split_bf16(float x, __nv_bfloat16& h, __nv_bfloat16& l) {
    h = __float2bfloat16_rn(x);
    l = __float2bfloat16_rn(x - __bfloat162float(h));
}

// ---------------- fast exp for x <= 0 ----------------
__device__ __forceinline__ float exp_neg(float x) {
    x = fmaxf(x, -87.0f);
    const float L2E = 1.4426950408889634f;
    float z = fmaf(x, L2E, 12582912.0f);
    int   ei = __float_as_int(z);
    float n = z - 12582912.0f;
    float f = fmaf(x, L2E, -n);
    float r = fmaf(1.5403530e-4f, f, 1.3333558e-3f);
    r = fmaf(r, f, 9.6181291e-3f);
    r = fmaf(r, f, 5.5504109e-2f);
    r = fmaf(r, f, 2.4022651e-1f);
    r = fmaf(r, f, 6.9314718e-1f);
    r = fmaf(r, f, 1.0f);
    float s = __int_as_float((ei + 127) << 23);
    return r * s;
}
__device__ __forceinline__ float elu_f(float v) { return v > 0.f ? v : exp_neg(v) - 1.f; }
__device__ __forceinline__ float lrelu(float e) { return e >= 0.f ? e : 0.2f * e; }

// ---------------- merged setup ----------------
__global__ void setup_all(const int* __restrict__ src, const float* __restrict__ W2,
                          const float* __restrict__ W3, const float* __restrict__ W1,
                          const float* __restrict__ as1, const float* __restrict__ ad1) {
    int bid = blockIdx.x, tid = threadIdx.x;
    if (bid < 540) {
        int i = bid * 256 + tid;
        int b = i / (NPG * 16);
        g_lsrc[i] = src[i] - b * NPG;
    } else if (bid < 1052) {
        int i = (bid - 540) * 256 + tid;
        split_bf16(W2[i], g_W2hi[i], g_W2lo[i]);
    } else if (bid < 1180) {
        int i = (bid - 1052) * 256 + tid;
        split_bf16(W3[i], g_W3hi[i], g_W3lo[i]);
    } else if (tid < 32) {
        int d = tid >> 4, h = (tid >> 1) & 7, f = tid & 1;
        const float* a = d ? ad1 : as1;
        float s = 0.f;
        #pragma unroll
        for (int c = 0; c < 64; c++) s += W1[f * 512 + h * 64 + c] * a[h * 64 + c];
        g_uv[tid] = s;
    }
}

// ---------------- layer 1: x -> z[TN,16] ----------------
__global__ __launch_bounds__(256)
void l1_z(const float* __restrict__ x) {
    __shared__ float xs[NPG * 2];
    __shared__ float es_s[NPG * 8];
    __shared__ float uvS[32];
    int blk = blockIdx.x;
    int chunk = blk & 7;
    int tb = blk >> 3;
    int b = tb & 7, t = tb >> 3;
    int base = t * N_NODES + b * NPG;
    int tid = threadIdx.x;
    if (tid < 32) uvS[tid] = g_uv[tid];
    for (int i = tid; i < NPG * 2; i += 256) xs[i] = x[(size_t)base * 2 + i];
    __syncthreads();
    for (int task = tid; task < NPG * 8; task += 256) {
        int n = task >> 3, h = task & 7;
        es_s[task] = fmaf(xs[n * 2], uvS[h * 2], xs[n * 2 + 1] * uvS[h * 2 + 1]);
    }
    __syncthreads();
    int n0 = chunk * 135;
    for (int task = tid; task < 135 * 8; task += 256) {
        int nl = task >> 3, h = task & 7;
        int n = n0 + nl;
        const int4* ls4 = (const int4*)(g_lsrc + ((size_t)b * NPG + n) * 16);
        int4 iA = ls4[0], iB = ls4[1], iC = ls4[2], iD = ls4[3];
        int idxs[16] = {iA.x, iA.y, iA.z, iA.w, iB.x, iB.y, iB.z, iB.w,
                        iC.x, iC.y, iC.z, iC.w, iD.x, iD.y, iD.z, iD.w};
        float ed = fmaf(xs[n * 2], uvS[16 + h * 2], xs[n * 2 + 1] * uvS[17 + h * 2]);
        float ev[17];
        float m = -1e30f;
        #pragma unroll
        for (int k = 0; k < 16; k++) {
            float e = lrelu(es_s[idxs[k] * 8 + h] + ed);
            ev[k] = e; m = fmaxf(m, e);
        }
        { float e = lrelu(es_s[n * 8 + h] + ed); ev[16] = e; m = fmaxf(m, e); }
        float ssum = 0.f;
        #pragma unroll
        for (int k = 0; k < 17; k++) { float v = exp_neg(ev[k] - m); ev[k] = v; ssum += v; }
        float inv = 1.f / (ssum + 1e-16f);
        float z0 = 0.f, z1 = 0.f;
        #pragma unroll
        for (int k = 0; k < 16; k++) {
            float a = ev[k] * inv;
            z0 = fmaf(a, xs[idxs[k] * 2], z0);
            z1 = fmaf(a, xs[idxs[k] * 2 + 1], z1);
        }
        {
            float a = ev[16] * inv;
            z0 = fmaf(a, xs[n * 2], z0);
            z1 = fmaf(a, xs[n * 2 + 1], z1);
        }
        *(float2*)&g_z[(size_t)(base + n) * 16 + h * 2] = make_float2(z0, z1);
    }
}

// ---------------- GEMM macros ----------------
#define MMA_BF16(d, a, b0, b1) \
    asm volatile("mma.sync.aligned.m16n8k16.row.col.f32.bf16.bf16.f32 " \
        "{%0,%1,%2,%3}, {%4,%5,%6,%7}, {%8,%9}, {%0,%1,%2,%3};" \
        : "+f"(d[0]), "+f"(d[1]), "+f"(d[2]), "+f"(d[3]) \
        : "r"(a[0]), "r"(a[1]), "r"(a[2]), "r"(a[3]), "r"(b0), "r"(b1))

#define LDMX4(r, addr) \
    asm volatile("ldmatrix.sync.aligned.m8n8.x4.shared.b16 {%0,%1,%2,%3}, [%4];" \
        : "=r"(r[0]), "=r"(r[1]), "=r"(r[2]), "=r"(r[3]) : "r"(addr))

#define LDMX4T(r, addr) \
    asm volatile("ldmatrix.sync.aligned.m8n8.x4.trans.shared.b16 {%0,%1,%2,%3}, [%4];" \
        : "=r"(r[0]), "=r"(r[1]), "=r"(r[2]), "=r"(r[3]) : "r"(addr))

#define CP16(dst, src) \
    asm volatile("cp.async.cg.shared.global [%0], [%1], 16;" :: "r"(dst), "l"(src))
#define CP_COMMIT asm volatile("cp.async.commit_group;")
#define CP_WAIT1  asm volatile("cp.async.wait_group 1;")
#define CP_WAIT0  asm volatile("cp.async.wait_group 0;")

#define ASTR 24
#define BSTR2 136

struct alignas(8) US4 { unsigned short v[4]; };

// ---------------- L2 GEMM with A generated from z (single-buffer sA) ----------------
__global__ __launch_bounds__(512)
void l1gemm_bf16(const float* __restrict__ W1, const float* __restrict__ b1,
                 const __nv_bfloat16* __restrict__ Whi, const __nv_bfloat16* __restrict__ Wlo,
                 float* __restrict__ C) {
    const int Nc = 256;
    __shared__ alignas(16) unsigned short sA[2][128 * ASTR];
    __shared__ alignas(16) unsigned short sB[3][2][16 * BSTR2];
    __shared__ float zs[128][16];
    __shared__ float W1s[1024], b1s[512];
    const int tid = threadIdx.x;
    const int lane = tid & 31, wid = tid >> 5;
    const int warpM = wid & 3, warpN = wid >> 2;
    const int rb = blockIdx.y * 128, cb = blockIdx.x * 128;
    const int hl = tid >> 8;
    const int j = tid & 255;
    const int brow = j >> 4, bcol = (j & 15) * 8;
    const __nv_bfloat16* bptr = (hl ? Wlo : Whi) + (size_t)brow * Nc + cb + bcol;
    unsigned sb_dst[3];
    #pragma unroll
    for (int s = 0; s < 3; s++)
        sb_dst[s] = (unsigned)__cvta_generic_to_shared(&sB[s][hl][brow * BSTR2 + bcol]);
    {
        int row = tid >> 2, q = tid & 3;
        *(float4*)&zs[row][q * 4] = *(const float4*)(g_z + (size_t)(rb + row) * 16 + q * 4);
    }
    for (int i = tid; i < 1024; i += 512) W1s[i] = W1[i];
    if (tid < 512) b1s[tid] = b1[tid];
    CP16(sb_dst[0], bptr);
    CP_COMMIT;
    CP16(sb_dst[1], bptr + (size_t)16 * Nc);
    CP_COMMIT;
    __syncthreads();

    const int arow = tid >> 2, ac0 = (tid & 3) * 4;
    const int a_r = (lane & 15);
    const int a_c = (lane >> 4) * 8;
    const int b_k = (lane & 7) + (lane & 8);
    const int b_n = (lane & 16) >> 1;
    float acc[2][4][4] = {};
    const int nk = 32;

    for (int ck = 0; ck < nk; ck++) {
        {
            int h = ck >> 2;
            float z0 = zs[arow][h * 2], z1 = zs[arow][h * 2 + 1];
            US4 hv, lv;
            #pragma unroll
            for (int i = 0; i < 4; i++) {
                int k = ck * 16 + ac0 + i;
                float v = elu_f(fmaf(z0, W1s[k], fmaf(z1, W1s[512 + k], b1s[k])));
                __nv_bfloat16 bh, bl;
                split_bf16(v, bh, bl);
                hv.v[i] = *(unsigned short*)&bh;
                lv.v[i] = *(unsigned short*)&bl;
            }
            *(US4*)&sA[0][arow * ASTR + ac0] = hv;
            *(US4*)&sA[1][arow * ASTR + ac0] = lv;
        }
        if (ck + 1 < nk) { CP_WAIT1; } else { CP_WAIT0; }
        __syncthreads();
        if (ck + 2 < nk) {
            int buf = (ck + 2) % 3;
            CP16(sb_dst[buf], bptr + (size_t)((ck + 2) * 16) * Nc);
            CP_COMMIT;
        }
        int p = ck % 3;
        unsigned ah[2][4], al[2][4];
        #pragma unroll
        for (int ma = 0; ma < 2; ma++) {
            int r = warpM * 32 + ma * 16 + a_r;
            unsigned adh = (unsigned)__cvta_generic_to_shared(&sA[0][r * ASTR + a_c]);
            unsigned adl = (unsigned)__cvta_generic_to_shared(&sA[1][r * ASTR + a_c]);
            LDMX4(ah[ma], adh);
            LDMX4(al[ma], adl);
        }
        unsigned bh[4][2], bl[4][2];
        #pragma unroll
        for (int g = 0; g < 2; g++) {
            int n0 = warpN * 32 + g * 16 + b_n;
            unsigned adh = (unsigned)__cvta_generic_to_shared(&sB[p][0][b_k * BSTR2 + n0]);
            unsigned adl = (unsigned)__cvta_generic_to_shared(&sB[p][1][b_k * BSTR2 + n0]);
            unsigned th[4], tl[4];
            LDMX4T(th, adh);
            LDMX4T(tl, adl);
            bh[g * 2][0] = th[0]; bh[g * 2][1] = th[1];
            bh[g * 2 + 1][0] = th[2]; bh[g * 2 + 1][1] = th[3];
            bl[g * 2][0] = tl[0]; bl[g * 2][1] = tl[1];
            bl[g * 2 + 1][0] = tl[2]; bl[g * 2 + 1][1] = tl[3];
        }
        #pragma unroll
        for (int ma = 0; ma < 2; ma++)
            #pragma unroll
            for (int na = 0; na < 4; na++) {
                MMA_BF16(acc[ma][na], ah[ma], bh[na][0], bh[na][1]);
                MMA_BF16(acc[ma][na], ah[ma], bl[na][0], bl[na][1]);
                MMA_BF16(acc[ma][na], al[ma], bh[na][0], bh[na][1]);
            }
        __syncthreads();
    }
    #pragma unroll
    for (int ma = 0; ma < 2; ma++)
        #pragma unroll
        for (int na = 0; na < 4; na++) {
            int r0 = rb + warpM * 32 + ma * 16 + (lane >> 2);
            int c = cb + warpN * 32 + na * 8 + (lane & 3) * 2;
            *(float2*)(C + (size_t)r0 * Nc + c)       = make_float2(acc[ma][na][0], acc[ma][na][1]);
            *(float2*)(C + (size_t)(r0 + 8) * Nc + c) = make_float2(acc[ma][na][2], acc[ma][na][3]);
        }
}

// ---------------- L3 GEMM: fp32 A split during staging ----------------
__global__ __launch_bounds__(512)
void gemm3_bf16(const float* __restrict__ A,
                const __nv_bfloat16* __restrict__ Whi, const __nv_bfloat16* __restrict__ Wlo,
                float* __restrict__ C) {
    const int K = 256, Nc = 128;
    __shared__ alignas(16) unsigned short sA[2][128 * ASTR];
    __shared__ alignas(16) unsigned short sB[3][2][16 * BSTR2];
    const int tid = threadIdx.x;
    const int lane = tid & 31, wid = tid >> 5;
    const int warpM = wid & 3, warpN = wid >> 2;
    const int rb = blockIdx.y * 128;
    const int hl = tid >> 8;
    const int j = tid & 255;
    const int brow = j >> 4, bcol = (j & 15) * 8;
    const __nv_bfloat16* bptr = (hl ? Wlo : Whi) + (size_t)brow * Nc + bcol;
    unsigned sb_dst[3];
    #pragma unroll
    for (int s = 0; s < 3; s++)
        sb_dst[s] = (unsigned)__cvta_generic_to_shared(&sB[s][hl][brow * BSTR2 + bcol]);
    const int arow = tid >> 2, ac0 = (tid & 3) * 4;
    const float* aptr = A + (size_t)(rb + arow) * K + ac0;
    CP16(sb_dst[0], bptr);
    CP_COMMIT;
    CP16(sb_dst[1], bptr + (size_t)16 * Nc);
    CP_COMMIT;
    float4 areg = *(const float4*)(aptr);
    const int a_r = (lane & 15);
    const int a_c = (lane >> 4) * 8;
    const int b_k = (lane & 7) + (lane & 8);
    const int b_n = (lane & 16) >> 1;
    float acc[2][4][4] = {};
    const int nk = 16;

    for (int ck = 0; ck < nk; ck++) {
        {
            US4 hv, lv;
            float vals[4] = {areg.x, areg.y, areg.z, areg.w};
            #pragma unroll
            for (int i = 0; i < 4; i++) {
                __nv_bfloat16 bh, bl;
                split_bf16(vals[i], bh, bl);
                hv.v[i] = *(unsigned short*)&bh;
                lv.v[i] = *(unsigned short*)&bl;
            }
            *(US4*)&sA[0][arow * ASTR + ac0] = hv;
            *(US4*)&sA[1][arow * ASTR + ac0] = lv;
        }
        if (ck + 1 < nk) { CP_WAIT1; } else { CP_WAIT0; }
        __syncthreads();
        if (ck + 1 < nk) areg = *(const float4*)(aptr + (ck + 1) * 16);
        if (ck + 2 < nk) {
            int buf = (ck + 2) % 3;
            CP16(sb_dst[buf], bptr + (size_t)((ck + 2) * 16) * Nc);
            CP_COMMIT;
        }
        int p = ck % 3;
        unsigned ah[2][4], al[2][4];
        #pragma unroll
        for (int ma = 0; ma < 2; ma++) {
            int r = warpM * 32 + ma * 16 + a_r;
            unsigned adh = (unsigned)__cvta_generic_to_shared(&sA[0][r * ASTR + a_c]);
            unsigned adl = (unsigned)__cvta_generic_to_shared(&sA[1][r * ASTR + a_c]);
            LDMX4(ah[ma], adh);
            LDMX4(al[ma], adl);
        }
        unsigned bh[4][2], bl[4][2];
        #pragma unroll
        for (int g = 0; g < 2; g++) {
            int n0 = warpN * 32 + g * 16 + b_n;
            unsigned adh = (unsigned)__cvta_generic_to_shared(&sB[p][0][b_k * BSTR2 + n0]);
            unsigned adl = (unsigned)__cvta_generic_to_shared(&sB[p][1][b_k * BSTR2 + n0]);
            unsigned th[4], tl[4];
            LDMX4T(th, adh);
            LDMX4T(tl, adl);
            bh[g * 2][0] = th[0]; bh[g * 2][1] = th[1];
            bh[g * 2 + 1][0] = th[2]; bh[g * 2 + 1][1] = th[3];
            bl[g * 2][0] = tl[0]; bl[g * 2][1] = tl[1];
            bl[g * 2 + 1][0] = tl[2]; bl[g * 2 + 1][1] = tl[3];
        }
        #pragma unroll
        for (int ma = 0; ma < 2; ma++)
            #pragma unroll
            for (int na = 0; na < 4; na++) {
                MMA_BF16(acc[ma][na], ah[ma], bh[na][0], bh[na][1]);
                MMA_BF16(acc[ma][na], ah[ma], bl[na][0], bl[na][1]);
                MMA_BF16(acc[ma][na], al[ma], bh[na][0], bh[na][1]);
            }
        __syncthreads();
    }
    #pragma unroll
    for (int ma = 0; ma < 2; ma++)
        #pragma unroll
        for (int na = 0; na < 4; na++) {
            int r0 = rb + warpM * 32 + ma * 16 + (lane >> 2);
            int c = warpN * 32 + na * 8 + (lane & 3) * 2;
            *(float2*)(C + (size_t)r0 * Nc + c)       = make_float2(acc[ma][na][0], acc[ma][na][1]);
            *(float2*)(C + (size_t)(r0 + 8) * Nc + c) = make_float2(acc[ma][na][2], acc[ma][na][3]);
        }
}

// ---------------- fully fused GAT (R14 form) ----------------
template<int H, int C, bool LSRC_SMEM>
__global__ __launch_bounds__(1024, 1)
void fused_gat(const float* __restrict__ Y, const float* __restrict__ as_,
               const float* __restrict__ ad_, const float* __restrict__ bias,
               float* __restrict__ Xout) {
    extern __shared__ float sm[];
    constexpr int HC = H * C;
    constexpr int Q = C / 4;
    float* tile   = sm;
    float* es_s   = tile + NPG * C;
    float* ed_s   = es_s + NPG;
    float* alphaS = ed_s + NPG;
    int*   lsrcS  = (int*)(alphaS + NPG * 17);
    __shared__ float as_s[C], ad_s[C], bi_s[C];
    int blk = blockIdx.x;
    int h = blk % H;
    int tb = blk / H;
    int b = tb % B_GR;
    int t = tb / B_GR;
    int base = t * N_NODES + b * NPG;
    int tid = threadIdx.x;
    const int* lg = g_lsrc + (size_t)b * NPG * 16;
    if (tid < C) { as_s[tid] = as_[h * C + tid]; ad_s[tid] = ad_[h * C + tid]; bi_s[tid] = bias[h * C + tid]; }
    for (int i = tid; i < NPG * Q; i += blockDim.x) {
        int n = i / Q, q = i % Q;
        *(float4*)&tile[n * C + q * 4] =
            *(const float4*)(Y + (size_t)(base + n) * HC + h * C + q * 4);
    }
    if (LSRC_SMEM) {
        for (int i = tid; i < NPG * 4; i += blockDim.x)
            ((int4*)lsrcS)[i] = ((const int4*)lg)[i];
    }
    __syncthreads();
    for (int n = tid; n < NPG; n += blockDim.x) {
        const float* tn = tile + n * C;
        int rot1 = tid & (Q - 1);
        float se = 0.f, de = 0.f;
        #pragma unroll
        for (int jj = 0; jj < Q; jj++) {
            int q = (jj + rot1) & (Q - 1);
            float4 v = *(const float4*)&tn[q * 4];
            float4 a = *(const float4*)&as_s[q * 4];
            float4 d = *(const float4*)&ad_s[q * 4];
            se = fmaf(v.x, a.x, fmaf(v.y, a.y, fmaf(v.z, a.z, fmaf(v.w, a.w, se))));
            de = fmaf(v.x, d.x, fmaf(v.y, d.y, fmaf(v.z, d.z, fmaf(v.w, d.w, de))));
        }
        es_s[n] = se; ed_s[n] = de;
    }
    __syncthreads();
    for (int n = tid; n < NPG; n += blockDim.x) {
        const int4* ls4 = LSRC_SMEM ? (const int4*)(lsrcS + n * 16)
                                    : (const int4*)(lg + n * 16);
        int4 iA = ls4[0], iB = ls4[1], iC_ = ls4[2], iD = ls4[3];
        int idxs[16] = {iA.x, iA.y, iA.z, iA.w, iB.x, iB.y, iB.z, iB.w,
                        iC_.x, iC_.y, iC_.z, iC_.w, iD.x, iD.y, iD.z, iD.w};
        float ed = ed_s[n];
        float m = lrelu(es_s[n] + ed);
        #pragma unroll
        for (int k = 0; k < 16; k++) m = fmaxf(m, lrelu(es_s[idxs[k]] + ed));
        float* ap = alphaS + n * 17;
        float ssum = 0.f;
        #pragma unroll
        for (int k = 0; k < 16; k++) {
            float v = exp_neg(lrelu(es_s[idxs[k]] + ed) - m);
            ap[k] = v; ssum += v;
        }
        { float v = exp_neg(lrelu(es_s[n] + ed) - m); ap[16] = v; ssum += v; }
        float inv = 1.f / (ssum + 1e-16f);
        #pragma unroll
        for (int k = 0; k < 17; k++) ap[k] *= inv;
    }
    __syncthreads();
    for (int task = tid; task < NPG * Q; task += blockDim.x) {
        int n = task / Q, q = task % Q;
        const float* ap = alphaS + n * 17;
        const int4* ls4 = LSRC_SMEM ? (const int4*)(lsrcS + n * 16)
                                    : (const int4*)(lg + n * 16);
        int4 iA = ls4[0], iB = ls4[1], iC_ = ls4[2], iD = ls4[3];
        int idxs[16] = {iA.x, iA.y, iA.z, iA.w, iB.x, iB.y, iB.z, iB.w,
                        iC_.x, iC_.y, iC_.z, iC_.w, iD.x, iD.y, iD.z, iD.w};
        float4 acc = make_float4(0.f, 0.f, 0.f, 0.f);
        #pragma unroll
        for (int k = 0; k < 16; k++) {
            float a = ap[k];
            float4 v = *(const float4*)&tile[idxs[k] * C + q * 4];
            acc.x = fmaf(a, v.x, acc.x); acc.y = fmaf(a, v.y, acc.y);
            acc.z = fmaf(a, v.z, acc.z); acc.w = fmaf(a, v.w, acc.w);
        }
        {
            float a = ap[16];
            float4 v = *(const float4*)&tile[n * C + q * 4];
            acc.x = fmaf(a, v.x, acc.x); acc.y = fmaf(a, v.y, acc.y);
            acc.z = fmaf(a, v.z, acc.z); acc.w = fmaf(a, v.w, acc.w);
        }
        float4 o;
        o.x = elu_f(acc.x + bi_s[q * 4 + 0]);
        o.y = elu_f(acc.y + bi_s[q * 4 + 1]);
        o.z = elu_f(acc.z + bi_s[q * 4 + 2]);
        o.w = elu_f(acc.w + bi_s[q * 4 + 3]);
        *(float4*)(Xout + (size_t)(base + n) * HC + h * C + q * 4) = o;
    }
}

// ---------------- fused layer 4: GEMM + GAT + pool ----------------
__global__ __launch_bounds__(1024, 1)
void l4_fused(const float* __restrict__ X, const float* __restrict__ W4,
              const float* __restrict__ as4, const float* __restrict__ ad4,
              const float* __restrict__ b4) {
    extern __shared__ float sm[];
    float* w4s    = sm;
    float* tile   = w4s + 1024;
    float* es_s   = tile + NPG * 8;
    float* ed_s   = es_s + NPG;
    float* alphaS = ed_s + NPG;
    int*   lsrcS  = (int*)(alphaS + NPG * 17);
    __shared__ float as_s[8], ad_s[8], bi_s[8];
    __shared__ float poolS[8];
    int tb = blockIdx.x;
    int b = tb % B_GR;
    int t = tb / B_GR;
    int base = t * N_NODES + b * NPG;
    int tid = threadIdx.x;
    if (tid < 8) { as_s[tid] = as4[tid]; ad_s[tid] = ad4[tid]; bi_s[tid] = b4[tid]; poolS[tid] = 0.f; }
    for (int i = tid; i < 1024; i += 1024) w4s[i] = W4[i];
    {
        const int* lg = g_lsrc + (size_t)b * NPG * 16;
        for (int i = tid; i < NPG * 4; i += 1024)
            ((int4*)lsrcS)[i] = ((const int4*)lg)[i];
    }
    __syncthreads();
    for (int n = tid; n < NPG; n += 1024) {
        const float4* xr = (const float4*)(X + (size_t)(base + n) * 128);
        float4 a0 = make_float4(0, 0, 0, 0), a1 = make_float4(0, 0, 0, 0);
        #pragma unroll 8
        for (int k4 = 0; k4 < 32; k4++) {
            float4 xv = xr[k4];
            float xsv[4] = {xv.x, xv.y, xv.z, xv.w};
            #pragma unroll
            for (int kk = 0; kk < 4; kk++) {
                float xs = xsv[kk];
                float4 w0 = *(const float4*)&w4s[(k4 * 4 + kk) * 8];
                float4 w1 = *(const float4*)&w4s[(k4 * 4 + kk) * 8 + 4];
                a0.x = fmaf(xs, w0.x, a0.x); a0.y = fmaf(xs, w0.y, a0.y);
                a0.z = fmaf(xs, w0.z, a0.z); a0.w = fmaf(xs, w0.w, a0.w);
                a1.x = fmaf(xs, w1.x, a1.x); a1.y = fmaf(xs, w1.y, a1.y);
                a1.z = fmaf(xs, w1.z, a1.z); a1.w = fmaf(xs, w1.w, a1.w);
            }
        }
        *(float4*)&tile[n * 8] = a0;
        *(float4*)&tile[n * 8 + 4] = a1;
    }
    __syncthreads();
    for (int n = tid; n < NPG; n += 1024) {
        const float* tn = tile + n * 8;
        float se = 0.f, de = 0.f;
        #pragma unroll
        for (int q = 0; q < 2; q++) {
            float4 v = *(const float4*)&tn[q * 4];
            float4 a = *(const float4*)&as_s[q * 4];
            float4 d = *(const float4*)&ad_s[q * 4];
            se = fmaf(v.x, a.x, fmaf(v.y, a.y, fmaf(v.z, a.z, fmaf(v.w, a.w, se))));
            de = fmaf(v.x, d.x, fmaf(v.y, d.y, fmaf(v.z, d.z, fmaf(v.w, d.w, de))));
        }
        es_s[n] = se; ed_s[n] = de;
    }
    __syncthreads();
    for (int n = tid; n < NPG; n += 1024) {
        const int4* ls4 = (const int4*)(lsrcS + n * 16);
        int4 iA = ls4[0], iB = ls4[1], iC_ = ls4[2], iD = ls4[3];
        int idxs[16] = {iA.x, iA.y, iA.z, iA.w, iB.x, iB.y, iB.z, iB.w,
                        iC_.x, iC_.y, iC_.z, iC_.w, iD.x, iD.y, iD.z, iD.w};
        float ed = ed_s[n];
        float m = lrelu(es_s[n] + ed);
        #pragma unroll
        for (int k = 0; k < 16; k++) m = fmaxf(m, lrelu(es_s[idxs[k]] + ed));
        float* ap = alphaS + n * 17;
        float ssum = 0.f;
        #pragma unroll
        for (int k = 0; k < 16; k++) {
            float v = exp_neg(lrelu(es_s[idxs[k]] + ed) - m);
            ap[k] = v; ssum += v;
        }
        { float v = exp_neg(lrelu(es_s[n] + ed) - m); ap[16] = v; ssum += v; }
        float inv = 1.f / (ssum + 1e-16f);
        #pragma unroll
        for (int k = 0; k < 17; k++) ap[k] *= inv;
    }
    __syncthreads();
    float psum[8] = {};
    for (int task = tid; task < NPG * 2; task += 1024) {
        int n = task >> 1, q = task & 1;
        const float* ap = alphaS + n * 17;
        const int4* ls4 = (const int4*)(lsrcS + n * 16);
        int4 iA = ls4[0], iB = ls4[1], iC_ = ls4[2], iD = ls4[3];
        int idxs[16] = {iA.x, iA.y, iA.z, iA.w, iB.x, iB.y, iB.z, iB.w,
                        iC_.x, iC_.y, iC_.z, iC_.w, iD.x, iD.y, iD.z, iD.w};
        float4 acc = make_float4(0.f, 0.f, 0.f, 0.f);
        #pragma unroll
        for (int k = 0; k < 16; k++) {
            float a = ap[k];
            float4 v = *(const float4*)&tile[idxs[k] * 8 + q * 4];
            acc.x = fmaf(a, v.x, acc.x); acc.y = fmaf(a, v.y, acc.y);
            acc.z = fmaf(a, v.z, acc.z); acc.w = fmaf(a, v.w, acc.w);
        }
        {
            float a = ap[16];
            float4 v = *(const float4*)&tile[n * 8 + q * 4];
            acc.x = fmaf(a, v.x, acc.x); acc.y = fmaf(a, v.y, acc.y);
            acc.z = fmaf(a, v.z, acc.z); acc.w = fmaf(a, v.w, acc.w);
        }
        psum[q * 4 + 0] += elu_f(acc.x + bi_s[q * 4 + 0]);
        psum[q * 4 + 1] += elu_f(acc.y + bi_s[q * 4 + 1]);
        psum[q * 4 + 2] += elu_f(acc.z + bi_s[q * 4 + 2]);
        psum[q * 4 + 3] += elu_f(acc.w + bi_s[q * 4 + 3]);
    }
    #pragma unroll
    for (int f = 0; f < 8; f++) {
        float v = psum[f];
        #pragma unroll
        for (int off = 16; off > 0; off >>= 1)
            v += __shfl_down_sync(0xffffffff, v, off);
        if ((tid & 31) == 0 && v != 0.f) atomicAdd(&poolS[f], v);
    }
    __syncthreads();
    if (tid < 8) g_emb[tb * 8 + tid] = poolS[tid] * (1.0f / (float)NPG);
}

// ---------------- LSTM + FC, batch-parallel (8 blocks) ----------------
__device__ __forceinline__ float sigmoidf(float x) { return 1.f / (1.f + expf(-x)); }

__global__ __launch_bounds__(512)
void lstm_fc8(const float* __restrict__ w_ih, const float* __restrict__ w_hh,
              const float* __restrict__ b_ih, const float* __restrict__ b_hh,
              const float* __restrict__ w_fc, const float* __restrict__ b_fc,
              float* __restrict__ out) {
    __shared__ float h[128], c[128], gbuf[512], xs[8];
    int b = blockIdx.x;          // batch element
    int r = threadIdx.x;         // gate row 0..511
    // hoist per-row constants
    float bias = b_ih[r] + b_hh[r];
    float wi[8];
    #pragma unroll
    for (int k = 0; k < 8; k++) wi[k] = w_ih[r * 8 + k];
    const float4* wh = (const float4*)(w_hh + (size_t)r * 128);
    if (r < 128) { h[r] = 0.f; c[r] = 0.f; }
    __syncthreads();
    for (int t = 0; t < T_STEPS; t++) {
        if (r < 8) xs[r] = g_emb[t * 64 + b * 8 + r];
        __syncthreads();
        float acc = bias;
        #pragma unroll
        for (int k = 0; k < 8; k++) acc = fmaf(xs[k], wi[k], acc);
        const float4* hb = (const float4*)h;
        #pragma unroll 8
        for (int jj = 0; jj < 32; jj++) {
            float4 w4 = wh[jj], h4 = hb[jj];
            acc = fmaf(w4.x, h4.x, acc); acc = fmaf(w4.y, h4.y, acc);
            acc = fmaf(w4.z, h4.z, acc); acc = fmaf(w4.w, h4.w, acc);
        }
        gbuf[r] = acc;
        __syncthreads();
        if (r < 128) {
            float ig = sigmoidf(gbuf[r]);
            float fg = sigmoidf(gbuf[128 + r]);
            float gg = tanhf(gbuf[256 + r]);
            float og = sigmoidf(gbuf[384 + r]);
            float cn = fg * c[r] + ig * gg;
            c[r] = cn;
            h[r] = og * tanhf(cn);
        }
        __syncthreads();
    }
    if (r < 2) {
        float acc = b_fc[r];
        const float* w = w_fc + r * 128;
        #pragma unroll 8
        for (int jj = 0; jj < 128; jj++) acc += h[jj] * w[jj];
        out[b * 2 + r] = acc;
    }
}

// ---------------- host launch ----------------
extern "C" void kernel_launch(void* const* d_in, const int* in_sizes, int n_in,
                              void* d_out, int out_size) {
    const float *x_seq = 0, *W1 = 0, *as1 = 0, *ad1 = 0, *b1 = 0;
    const float *W2 = 0, *as2 = 0, *ad2 = 0, *b2 = 0;
    const float *W3 = 0, *as3 = 0, *ad3 = 0, *b3 = 0;
    const float *W4 = 0, *as4 = 0, *ad4 = 0, *b4 = 0;
    const float *w_ih = 0, *w_hh = 0, *b_ih = 0, *b_hh = 0, *w_fc = 0, *b_fc = 0;
    const int *edge = 0;
    int c1024 = 0, c512 = 0, c256 = 0, c128 = 0, c8 = 0;
    for (int i = 0; i < n_in; i++) {
        const float* p = (const float*)d_in[i];
        switch (in_sizes[i]) {
            case 172800: x_seq = p; break;
            case 276480: edge = (const int*)p; break;
            case 8640:   break;
            case 131072: W2 = p; break;
            case 65536:  w_hh = p; break;
            case 32768:  W3 = p; break;
            case 4096:   w_ih = p; break;
            case 1024:   { if (c1024++ == 0) W1 = p; else W4 = p; } break;
            case 512: { int k = c512++;
                if (k == 0) as1 = p; else if (k == 1) ad1 = p; else if (k == 2) b1 = p;
                else if (k == 3) b_ih = p; else b_hh = p; } break;
            case 256: { int k = c256++;
                if (k == 0) as2 = p; else if (k == 1) ad2 = p; else if (k == 2) b2 = p;
                else w_fc = p; } break;
            case 128: { int k = c128++;
                if (k == 0) as3 = p; else if (k == 1) ad3 = p; else b3 = p; } break;
            case 8: { int k = c8++;
                if (k == 0) as4 = p; else if (k == 1) ad4 = p; else b4 = p; } break;
            case 2: b_fc = p; break;
            default: break;
        }
    }
    const int* src = edge;

    float *bufA, *bufB;
    __nv_bfloat16 *W2hi, *W2lo, *W3hi, *W3lo;
    cudaGetSymbolAddress((void**)&bufA, g_bufA);
    cudaGetSymbolAddress((void**)&bufB, g_bufB);
    cudaGetSymbolAddress((void**)&W2hi, g_W2hi);
    cudaGetSymbolAddress((void**)&W2lo, g_W2lo);
    cudaGetSymbolAddress((void**)&W3hi, g_W3hi);
    cudaGetSymbolAddress((void**)&W3lo, g_W3lo);

    const int SM_F32 = (NPG * 32 + NPG * 2 + NPG * 17) * 4;
    const int SM_F16 = (NPG * 16 + NPG * 2 + NPG * 17 + NPG * 16) * 4;
    const int SM_L4  = (1024 + NPG * 8 + NPG * 2 + NPG * 17 + NPG * 16) * 4;
    cudaFuncSetAttribute(fused_gat<8, 32, false>, cudaFuncAttributeMaxDynamicSharedMemorySize, SM_F32);
    cudaFuncSetAttribute(fused_gat<8, 16, true>,  cudaFuncAttributeMaxDynamicSharedMemorySize, SM_F16);
    cudaFuncSetAttribute(l4_fused, cudaFuncAttributeMaxDynamicSharedMemorySize, SM_L4);

    // 1: merged setup
    setup_all<<<1181, 256>>>(src, W2, W3, W1, as1, ad1);
    // 2: layer-1 z
    l1_z<<<640, 256>>>(x_seq);
    // 3: L2 GEMM
    l1gemm_bf16<<<dim3(2, TN / 128), 512>>>(W1, b1, W2hi, W2lo, bufA);
    // 4 (PROFILED): GAT layer 2
    fused_gat<8, 32, false><<<T_STEPS * B_GR * 8, 1024, SM_F32>>>(bufA, as2, ad2, b2, bufB);
    // 5: L3 GEMM
    gemm3_bf16<<<dim3(1, TN / 128), 512>>>(bufB, W3hi, W3lo, bufA);
    // 6: GAT layer 3
    fused_gat<8, 16, true><<<T_STEPS * B_GR * 8, 1024, SM_F16>>>(bufA, as3, ad3, b3, bufB);
    // 7: fused layer 4
    l4_fused<<<T_STEPS * B_GR, 1024, SM_L4>>>(bufB, W4, as4, ad4, b4);
    // 8: LSTM + FC (batch-parallel)
    lstm_fc8<<<B_GR, 512>>>(w_ih, w_hh, b_ih, b_hh, w_fc, b_fc, (float*)d_out);
}

// round 16
// speedup vs baseline: 2.1992x; 1.1434x over previous
#include <cuda_runtime.h>
#include <cuda_fp16.h>
#include <math.h>

#define T_STEPS 10
#define B_GR    8
#define NPG     1080
#define N_NODES 8640
#define TN      86400
#define DEG     16

// ---------------- scratch ----------------
__device__ float g_bufA[(size_t)TN * 256];
__device__ float g_bufB[(size_t)TN * 256];
__device__ float g_z[TN * 16];
__device__ __half g_W2h[512 * 256];
__device__ __half g_W3h[256 * 128];
__device__ float g_emb[T_STEPS * B_GR * 8];
__device__ float g_uv[32];
__device__ int   g_lsrc[N_NODES * 16];

// ---------------- fast exp for x <= 0 ----------------
__device__ __forceinline__ float exp_neg(float x) {
    x = fmaxf(x, -87.0f);
    const float L2E = 1.4426950408889634f;
    float z = fmaf(x, L2E, 12582912.0f);
    int   ei = __float_as_int(z);
    float n = z - 12582912.0f;
    float f = fmaf(x, L2E, -n);
    float r = fmaf(1.5403530e-4f, f, 1.3333558e-3f);
    r = fmaf(r, f, 9.6181291e-3f);
    r = fmaf(r, f, 5.5504109e-2f);
    r = fmaf(r, f, 2.4022651e-1f);
    r = fmaf(r, f, 6.9314718e-1f);
    r = fmaf(r, f, 1.0f);
    float s = __int_as_float((ei + 127) << 23);
    return r * s;
}
__device__ __forceinline__ float elu_f(float v) { return v > 0.f ? v : exp_neg(v) - 1.f; }
__device__ __forceinline__ float lrelu(float e) { return e >= 0.f ? e : 0.2f * e; }

// ---------------- merged setup ----------------
__global__ void setup_all(const int* __restrict__ src, const float* __restrict__ W2,
                          const float* __restrict__ W3, const float* __restrict__ W1,
                          const float* __restrict__ as1, const float* __restrict__ ad1) {
    int bid = blockIdx.x, tid = threadIdx.x;
    if (bid < 540) {
        int i = bid * 256 + tid;
        int b = i / (NPG * 16);
        g_lsrc[i] = src[i] - b * NPG;
    } else if (bid < 1052) {
        int i = (bid - 540) * 256 + tid;
        g_W2h[i] = __float2half_rn(W2[i]);
    } else if (bid < 1180) {
        int i = (bid - 1052) * 256 + tid;
        g_W3h[i] = __float2half_rn(W3[i]);
    } else if (tid < 32) {
        int d = tid >> 4, h = (tid >> 1) & 7, f = tid & 1;
        const float* a = d ? ad1 : as1;
        float s = 0.f;
        #pragma unroll
        for (int c = 0; c < 64; c++) s += W1[f * 512 + h * 64 + c] * a[h * 64 + c];
        g_uv[tid] = s;
    }
}

// ---------------- layer 1: x -> z[TN,16] ----------------
__global__ __launch_bounds__(256)
void l1_z(const float* __restrict__ x) {
    __shared__ float xs[NPG * 2];
    __shared__ float es_s[NPG * 8];
    __shared__ float uvS[32];
    int blk = blockIdx.x;
    int chunk = blk & 7;
    int tb = blk >> 3;
    int b = tb & 7, t = tb >> 3;
    int base = t * N_NODES + b * NPG;
    int tid = threadIdx.x;
    if (tid < 32) uvS[tid] = g_uv[tid];
    for (int i = tid; i < NPG * 2; i += 256) xs[i] = x[(size_t)base * 2 + i];
    __syncthreads();
    for (int task = tid; task < NPG * 8; task += 256) {
        int n = task >> 3, h = task & 7;
        es_s[task] = fmaf(xs[n * 2], uvS[h * 2], xs[n * 2 + 1] * uvS[h * 2 + 1]);
    }
    __syncthreads();
    int n0 = chunk * 135;
    for (int task = tid; task < 135 * 8; task += 256) {
        int nl = task >> 3, h = task & 7;
        int n = n0 + nl;
        const int4* ls4 = (const int4*)(g_lsrc + ((size_t)b * NPG + n) * 16);
        int4 iA = ls4[0], iB = ls4[1], iC = ls4[2], iD = ls4[3];
        int idxs[16] = {iA.x, iA.y, iA.z, iA.w, iB.x, iB.y, iB.z, iB.w,
                        iC.x, iC.y, iC.z, iC.w, iD.x, iD.y, iD.z, iD.w};
        float ed = fmaf(xs[n * 2], uvS[16 + h * 2], xs[n * 2 + 1] * uvS[17 + h * 2]);
        float ev[17];
        float m = -1e30f;
        #pragma unroll
        for (int k = 0; k < 16; k++) {
            float e = lrelu(es_s[idxs[k] * 8 + h] + ed);
            ev[k] = e; m = fmaxf(m, e);
        }
        { float e = lrelu(es_s[n * 8 + h] + ed); ev[16] = e; m = fmaxf(m, e); }
        float ssum = 0.f;
        #pragma unroll
        for (int k = 0; k < 17; k++) { float v = exp_neg(ev[k] - m); ev[k] = v; ssum += v; }
        float inv = 1.f / (ssum + 1e-16f);
        float z0 = 0.f, z1 = 0.f;
        #pragma unroll
        for (int k = 0; k < 16; k++) {
            float a = ev[k] * inv;
            z0 = fmaf(a, xs[idxs[k] * 2], z0);
            z1 = fmaf(a, xs[idxs[k] * 2 + 1], z1);
        }
        {
            float a = ev[16] * inv;
            z0 = fmaf(a, xs[n * 2], z0);
            z1 = fmaf(a, xs[n * 2 + 1], z1);
        }
        *(float2*)&g_z[(size_t)(base + n) * 16 + h * 2] = make_float2(z0, z1);
    }
}

// ---------------- GEMM macros ----------------
#define MMA_FP16(d, a, b0, b1) \
    asm volatile("mma.sync.aligned.m16n8k16.row.col.f32.f16.f16.f32 " \
        "{%0,%1,%2,%3}, {%4,%5,%6,%7}, {%8,%9}, {%0,%1,%2,%3};" \
        : "+f"(d[0]), "+f"(d[1]), "+f"(d[2]), "+f"(d[3]) \
        : "r"(a[0]), "r"(a[1]), "r"(a[2]), "r"(a[3]), "r"(b0), "r"(b1))

#define LDMX4(r, addr) \
    asm volatile("ldmatrix.sync.aligned.m8n8.x4.shared.b16 {%0,%1,%2,%3}, [%4];" \
        : "=r"(r[0]), "=r"(r[1]), "=r"(r[2]), "=r"(r[3]) : "r"(addr))

#define LDMX4T(r, addr) \
    asm volatile("ldmatrix.sync.aligned.m8n8.x4.trans.shared.b16 {%0,%1,%2,%3}, [%4];" \
        : "=r"(r[0]), "=r"(r[1]), "=r"(r[2]), "=r"(r[3]) : "r"(addr))

#define CP16(dst, src) \
    asm volatile("cp.async.cg.shared.global [%0], [%1], 16;" :: "r"(dst), "l"(src))
#define CP_COMMIT asm volatile("cp.async.commit_group;")
#define CP_WAIT1  asm volatile("cp.async.wait_group 1;")
#define CP_WAIT0  asm volatile("cp.async.wait_group 0;")

#define ASTR 24
#define BSTR2 136

struct alignas(8) US4 { unsigned short v[4]; };

// ---------------- L2 GEMM fp16, A generated from z ----------------
__global__ __launch_bounds__(512)
void l1gemm_fp16(const float* __restrict__ W1, const float* __restrict__ b1,
                 const __half* __restrict__ W, float* __restrict__ C) {
    const int Nc = 256;
    __shared__ alignas(16) unsigned short sA[128 * ASTR];
    __shared__ alignas(16) unsigned short sB[3][16 * BSTR2];
    __shared__ float zs[128][16];
    __shared__ float W1s[1024], b1s[512];
    const int tid = threadIdx.x;
    const int lane = tid & 31, wid = tid >> 5;
    const int warpM = wid & 3, warpN = wid >> 2;
    const int rb = blockIdx.y * 128, cb = blockIdx.x * 128;
    const int j = tid & 255;
    const int brow = j >> 4, bcol = (j & 15) * 8;
    const bool doB = (tid < 256);
    const __half* bptr = W + (size_t)brow * Nc + cb + bcol;
    unsigned sb_dst[3];
    #pragma unroll
    for (int s = 0; s < 3; s++)
        sb_dst[s] = (unsigned)__cvta_generic_to_shared(&sB[s][brow * BSTR2 + bcol]);
    {
        int row = tid >> 2, q = tid & 3;
        *(float4*)&zs[row][q * 4] = *(const float4*)(g_z + (size_t)(rb + row) * 16 + q * 4);
    }
    for (int i = tid; i < 1024; i += 512) W1s[i] = W1[i];
    if (tid < 512) b1s[tid] = b1[tid];
    if (doB) { CP16(sb_dst[0], bptr); }
    CP_COMMIT;
    if (doB) { CP16(sb_dst[1], bptr + (size_t)16 * Nc); }
    CP_COMMIT;
    __syncthreads();

    const int arow = tid >> 2, ac0 = (tid & 3) * 4;
    const int a_r = (lane & 15);
    const int a_c = (lane >> 4) * 8;
    const int b_k = (lane & 7) + (lane & 8);
    const int b_n = (lane & 16) >> 1;
    float acc[2][4][4] = {};
    const int nk = 32;

    for (int ck = 0; ck < nk; ck++) {
        // generate A(ck) tile as fp16
        {
            int h = ck >> 2;
            float z0 = zs[arow][h * 2], z1 = zs[arow][h * 2 + 1];
            US4 hv;
            #pragma unroll
            for (int i = 0; i < 4; i++) {
                int k = ck * 16 + ac0 + i;
                float v = elu_f(fmaf(z0, W1s[k], fmaf(z1, W1s[512 + k], b1s[k])));
                __half hh = __float2half_rn(v);
                hv.v[i] = *(unsigned short*)&hh;
            }
            *(US4*)&sA[arow * ASTR + ac0] = hv;
        }
        if (ck + 1 < nk) { CP_WAIT1; } else { CP_WAIT0; }
        __syncthreads();
        if (ck + 2 < nk) {
            int buf = (ck + 2) % 3;
            if (doB) { CP16(sb_dst[buf], bptr + (size_t)((ck + 2) * 16) * Nc); }
            CP_COMMIT;
        }
        int p = ck % 3;
        unsigned ah[2][4];
        #pragma unroll
        for (int ma = 0; ma < 2; ma++) {
            int r = warpM * 32 + ma * 16 + a_r;
            unsigned ad = (unsigned)__cvta_generic_to_shared(&sA[r * ASTR + a_c]);
            LDMX4(ah[ma], ad);
        }
        unsigned bh[4][2];
        #pragma unroll
        for (int g = 0; g < 2; g++) {
            int n0 = warpN * 32 + g * 16 + b_n;
            unsigned ad = (unsigned)__cvta_generic_to_shared(&sB[p][b_k * BSTR2 + n0]);
            unsigned th[4];
            LDMX4T(th, ad);
            bh[g * 2][0] = th[0]; bh[g * 2][1] = th[1];
            bh[g * 2 + 1][0] = th[2]; bh[g * 2 + 1][1] = th[3];
        }
        #pragma unroll
        for (int ma = 0; ma < 2; ma++)
            #pragma unroll
            for (int na = 0; na < 4; na++)
                MMA_FP16(acc[ma][na], ah[ma], bh[na][0], bh[na][1]);
        __syncthreads();
    }
    #pragma unroll
    for (int ma = 0; ma < 2; ma++)
        #pragma unroll
        for (int na = 0; na < 4; na++) {
            int r0 = rb + warpM * 32 + ma * 16 + (lane >> 2);
            int c = cb + warpN * 32 + na * 8 + (lane & 3) * 2;
            *(float2*)(C + (size_t)r0 * Nc + c)       = make_float2(acc[ma][na][0], acc[ma][na][1]);
            *(float2*)(C + (size_t)(r0 + 8) * Nc + c) = make_float2(acc[ma][na][2], acc[ma][na][3]);
        }
}

// ---------------- L3 GEMM fp16: fp32 A converted during staging ----------------
__global__ __launch_bounds__(512)
void gemm3_fp16(const float* __restrict__ A, const __half* __restrict__ W,
                float* __restrict__ C) {
    const int K = 256, Nc = 128;
    __shared__ alignas(16) unsigned short sA[128 * ASTR];
    __shared__ alignas(16) unsigned short sB[3][16 * BSTR2];
    const int tid = threadIdx.x;
    const int lane = tid & 31, wid = tid >> 5;
    const int warpM = wid & 3, warpN = wid >> 2;
    const int rb = blockIdx.y * 128;
    const int j = tid & 255;
    const int brow = j >> 4, bcol = (j & 15) * 8;
    const bool doB = (tid < 256);
    const __half* bptr = W + (size_t)brow * Nc + bcol;
    unsigned sb_dst[3];
    #pragma unroll
    for (int s = 0; s < 3; s++)
        sb_dst[s] = (unsigned)__cvta_generic_to_shared(&sB[s][brow * BSTR2 + bcol]);
    const int arow = tid >> 2, ac0 = (tid & 3) * 4;
    const float* aptr = A + (size_t)(rb + arow) * K + ac0;
    if (doB) { CP16(sb_dst[0], bptr); }
    CP_COMMIT;
    if (doB) { CP16(sb_dst[1], bptr + (size_t)16 * Nc); }
    CP_COMMIT;
    float4 areg = *(const float4*)(aptr);
    const int a_r = (lane & 15);
    const int a_c = (lane >> 4) * 8;
    const int b_k = (lane & 7) + (lane & 8);
    const int b_n = (lane & 16) >> 1;
    float acc[2][4][4] = {};
    const int nk = 16;

    for (int ck = 0; ck < nk; ck++) {
        {
            US4 hv;
            float vals[4] = {areg.x, areg.y, areg.z, areg.w};
            #pragma unroll
            for (int i = 0; i < 4; i++) {
                __half hh = __float2half_rn(vals[i]);
                hv.v[i] = *(unsigned short*)&hh;
            }
            *(US4*)&sA[arow * ASTR + ac0] = hv;
        }
        if (ck + 1 < nk) { CP_WAIT1; } else { CP_WAIT0; }
        __syncthreads();
        if (ck + 1 < nk) areg = *(const float4*)(aptr + (ck + 1) * 16);
        if (ck + 2 < nk) {
            int buf = (ck + 2) % 3;
            if (doB) { CP16(sb_dst[buf], bptr + (size_t)((ck + 2) * 16) * Nc); }
            CP_COMMIT;
        }
        int p = ck % 3;
        unsigned ah[2][4];
        #pragma unroll
        for (int ma = 0; ma < 2; ma++) {
            int r = warpM * 32 + ma * 16 + a_r;
            unsigned ad = (unsigned)__cvta_generic_to_shared(&sA[r * ASTR + a_c]);
            LDMX4(ah[ma], ad);
        }
        unsigned bh[4][2];
        #pragma unroll
        for (int g = 0; g < 2; g++) {
            int n0 = warpN * 32 + g * 16 + b_n;
            unsigned ad = (unsigned)__cvta_generic_to_shared(&sB[p][b_k * BSTR2 + n0]);
            unsigned th[4];
            LDMX4T(th, ad);
            bh[g * 2][0] = th[0]; bh[g * 2][1] = th[1];
            bh[g * 2 + 1][0] = th[2]; bh[g * 2 + 1][1] = th[3];
        }
        #pragma unroll
        for (int ma = 0; ma < 2; ma++)
            #pragma unroll
            for (int na = 0; na < 4; na++)
                MMA_FP16(acc[ma][na], ah[ma], bh[na][0], bh[na][1]);
        __syncthreads();
    }
    #pragma unroll
    for (int ma = 0; ma < 2; ma++)
        #pragma unroll
        for (int na = 0; na < 4; na++) {
            int r0 = rb + warpM * 32 + ma * 16 + (lane >> 2);
            int c = warpN * 32 + na * 8 + (lane & 3) * 2;
            *(float2*)(C + (size_t)r0 * Nc + c)       = make_float2(acc[ma][na][0], acc[ma][na][1]);
            *(float2*)(C + (size_t)(r0 + 8) * Nc + c) = make_float2(acc[ma][na][2], acc[ma][na][3]);
        }
}

// ---------------- fully fused GAT (R15 form) ----------------
template<int H, int C, bool LSRC_SMEM>
__global__ __launch_bounds__(1024, 1)
void fused_gat(const float* __restrict__ Y, const float* __restrict__ as_,
               const float* __restrict__ ad_, const float* __restrict__ bias,
               float* __restrict__ Xout) {
    extern __shared__ float sm[];
    constexpr int HC = H * C;
    constexpr int Q = C / 4;
    float* tile   = sm;
    float* es_s   = tile + NPG * C;
    float* ed_s   = es_s + NPG;
    float* alphaS = ed_s + NPG;
    int*   lsrcS  = (int*)(alphaS + NPG * 17);
    __shared__ float as_s[C], ad_s[C], bi_s[C];
    int blk = blockIdx.x;
    int h = blk % H;
    int tb = blk / H;
    int b = tb % B_GR;
    int t = tb / B_GR;
    int base = t * N_NODES + b * NPG;
    int tid = threadIdx.x;
    const int* lg = g_lsrc + (size_t)b * NPG * 16;
    if (tid < C) { as_s[tid] = as_[h * C + tid]; ad_s[tid] = ad_[h * C + tid]; bi_s[tid] = bias[h * C + tid]; }
    for (int i = tid; i < NPG * Q; i += blockDim.x) {
        int n = i / Q, q = i % Q;
        *(float4*)&tile[n * C + q * 4] =
            *(const float4*)(Y + (size_t)(base + n) * HC + h * C + q * 4);
    }
    if (LSRC_SMEM) {
        for (int i = tid; i < NPG * 4; i += blockDim.x)
            ((int4*)lsrcS)[i] = ((const int4*)lg)[i];
    }
    __syncthreads();
    for (int n = tid; n < NPG; n += blockDim.x) {
        const float* tn = tile + n * C;
        int rot1 = tid & (Q - 1);
        float se = 0.f, de = 0.f;
        #pragma unroll
        for (int jj = 0; jj < Q; jj++) {
            int q = (jj + rot1) & (Q - 1);
            float4 v = *(const float4*)&tn[q * 4];
            float4 a = *(const float4*)&as_s[q * 4];
            float4 d = *(const float4*)&ad_s[q * 4];
            se = fmaf(v.x, a.x, fmaf(v.y, a.y, fmaf(v.z, a.z, fmaf(v.w, a.w, se))));
            de = fmaf(v.x, d.x, fmaf(v.y, d.y, fmaf(v.z, d.z, fmaf(v.w, d.w, de))));
        }
        es_s[n] = se; ed_s[n] = de;
    }
    __syncthreads();
    for (int n = tid; n < NPG; n += blockDim.x) {
        const int4* ls4 = LSRC_SMEM ? (const int4*)(lsrcS + n * 16)
                                    : (const int4*)(lg + n * 16);
        int4 iA = ls4[0], iB = ls4[1], iC_ = ls4[2], iD = ls4[3];
        int idxs[16] = {iA.x, iA.y, iA.z, iA.w, iB.x, iB.y, iB.z, iB.w,
                        iC_.x, iC_.y, iC_.z, iC_.w, iD.x, iD.y, iD.z, iD.w};
        float ed = ed_s[n];
        float m = lrelu(es_s[n] + ed);
        #pragma unroll
        for (int k = 0; k < 16; k++) m = fmaxf(m, lrelu(es_s[idxs[k]] + ed));
        float* ap = alphaS + n * 17;
        float ssum = 0.f;
        #pragma unroll
        for (int k = 0; k < 16; k++) {
            float v = exp_neg(lrelu(es_s[idxs[k]] + ed) - m);
            ap[k] = v; ssum += v;
        }
        { float v = exp_neg(lrelu(es_s[n] + ed) - m); ap[16] = v; ssum += v; }
        float inv = 1.f / (ssum + 1e-16f);
        #pragma unroll
        for (int k = 0; k < 17; k++) ap[k] *= inv;
    }
    __syncthreads();
    for (int task = tid; task < NPG * Q; task += blockDim.x) {
        int n = task / Q, q = task % Q;
        const float* ap = alphaS + n * 17;
        const int4* ls4 = LSRC_SMEM ? (const int4*)(lsrcS + n * 16)
                                    : (const int4*)(lg + n * 16);
        int4 iA = ls4[0], iB = ls4[1], iC_ = ls4[2], iD = ls4[3];
        int idxs[16] = {iA.x, iA.y, iA.z, iA.w, iB.x, iB.y, iB.z, iB.w,
                        iC_.x, iC_.y, iC_.z, iC_.w, iD.x, iD.y, iD.z, iD.w};
        float4 acc = make_float4(0.f, 0.f, 0.f, 0.f);
        #pragma unroll
        for (int k = 0; k < 16; k++) {
            float a = ap[k];
            float4 v = *(const float4*)&tile[idxs[k] * C + q * 4];
            acc.x = fmaf(a, v.x, acc.x); acc.y = fmaf(a, v.y, acc.y);
            acc.z = fmaf(a, v.z, acc.z); acc.w = fmaf(a, v.w, acc.w);
        }
        {
            float a = ap[16];
            float4 v = *(const float4*)&tile[n * C + q * 4];
            acc.x = fmaf(a, v.x, acc.x); acc.y = fmaf(a, v.y, acc.y);
            acc.z = fmaf(a, v.z, acc.z); acc.w = fmaf(a, v.w, acc.w);
        }
        float4 o;
        o.x = elu_f(acc.x + bi_s[q * 4 + 0]);
        o.y = elu_f(acc.y + bi_s[q * 4 + 1]);
        o.z = elu_f(acc.z + bi_s[q * 4 + 2]);
        o.w = elu_f(acc.w + bi_s[q * 4 + 3]);
        *(float4*)(Xout + (size_t)(base + n) * HC + h * C + q * 4) = o;
    }
}

// ---------------- fused layer 4: GEMM + GAT + pool ----------------
__global__ __launch_bounds__(1024, 1)
void l4_fused(const float* __restrict__ X, const float* __restrict__ W4,
              const float* __restrict__ as4, const float* __restrict__ ad4,
              const float* __restrict__ b4) {
    extern __shared__ float sm[];
    float* w4s    = sm;
    float* tile   = w4s + 1024;
    float* es_s   = tile + NPG * 8;
    float* ed_s   = es_s + NPG;
    float* alphaS = ed_s + NPG;
    int*   lsrcS  = (int*)(alphaS + NPG * 17);
    __shared__ float as_s[8], ad_s[8], bi_s[8];
    __shared__ float poolS[8];
    int tb = blockIdx.x;
    int b = tb % B_GR;
    int t = tb / B_GR;
    int base = t * N_NODES + b * NPG;
    int tid = threadIdx.x;
    if (tid < 8) { as_s[tid] = as4[tid]; ad_s[tid] = ad4[tid]; bi_s[tid] = b4[tid]; poolS[tid] = 0.f; }
    for (int i = tid; i < 1024; i += 1024) w4s[i] = W4[i];
    {
        const int* lg = g_lsrc + (size_t)b * NPG * 16;
        for (int i = tid; i < NPG * 4; i += 1024)
            ((int4*)lsrcS)[i] = ((const int4*)lg)[i];
    }
    __syncthreads();
    for (int n = tid; n < NPG; n += 1024) {
        const float4* xr = (const float4*)(X + (size_t)(base + n) * 128);
        float4 a0 = make_float4(0, 0, 0, 0), a1 = make_float4(0, 0, 0, 0);
        #pragma unroll 8
        for (int k4 = 0; k4 < 32; k4++) {
            float4 xv = xr[k4];
            float xsv[4] = {xv.x, xv.y, xv.z, xv.w};
            #pragma unroll
            for (int kk = 0; kk < 4; kk++) {
                float xs = xsv[kk];
                float4 w0 = *(const float4*)&w4s[(k4 * 4 + kk) * 8];
                float4 w1 = *(const float4*)&w4s[(k4 * 4 + kk) * 8 + 4];
                a0.x = fmaf(xs, w0.x, a0.x); a0.y = fmaf(xs, w0.y, a0.y);
                a0.z = fmaf(xs, w0.z, a0.z); a0.w = fmaf(xs, w0.w, a0.w);
                a1.x = fmaf(xs, w1.x, a1.x); a1.y = fmaf(xs, w1.y, a1.y);
                a1.z = fmaf(xs, w1.z, a1.z); a1.w = fmaf(xs, w1.w, a1.w);
            }
        }
        *(float4*)&tile[n * 8] = a0;
        *(float4*)&tile[n * 8 + 4] = a1;
    }
    __syncthreads();
    for (int n = tid; n < NPG; n += 1024) {
        const float* tn = tile + n * 8;
        float se = 0.f, de = 0.f;
        #pragma unroll
        for (int q = 0; q < 2; q++) {
            float4 v = *(const float4*)&tn[q * 4];
            float4 a = *(const float4*)&as_s[q * 4];
            float4 d = *(const float4*)&ad_s[q * 4];
            se = fmaf(v.x, a.x, fmaf(v.y, a.y, fmaf(v.z, a.z, fmaf(v.w, a.w, se))));
            de = fmaf(v.x, d.x, fmaf(v.y, d.y, fmaf(v.z, d.z, fmaf(v.w, d.w, de))));
        }
        es_s[n] = se; ed_s[n] = de;
    }
    __syncthreads();
    for (int n = tid; n < NPG; n += 1024) {
        const int4* ls4 = (const int4*)(lsrcS + n * 16);
        int4 iA = ls4[0], iB = ls4[1], iC_ = ls4[2], iD = ls4[3];
        int idxs[16] = {iA.x, iA.y, iA.z, iA.w, iB.x, iB.y, iB.z, iB.w,
                        iC_.x, iC_.y, iC_.z, iC_.w, iD.x, iD.y, iD.z, iD.w};
        float ed = ed_s[n];
        float m = lrelu(es_s[n] + ed);
        #pragma unroll
        for (int k = 0; k < 16; k++) m = fmaxf(m, lrelu(es_s[idxs[k]] + ed));
        float* ap = alphaS + n * 17;
        float ssum = 0.f;
        #pragma unroll
        for (int k = 0; k < 16; k++) {
            float v = exp_neg(lrelu(es_s[idxs[k]] + ed) - m);
            ap[k] = v; ssum += v;
        }
        { float v = exp_neg(lrelu(es_s[n] + ed) - m); ap[16] = v; ssum += v; }
        float inv = 1.f / (ssum + 1e-16f);
        #pragma unroll
        for (int k = 0; k < 17; k++) ap[k] *= inv;
    }
    __syncthreads();
    float psum[8] = {};
    for (int task = tid; task < NPG * 2; task += 1024) {
        int n = task >> 1, q = task & 1;
        const float* ap = alphaS + n * 17;
        const int4* ls4 = (const int4*)(lsrcS + n * 16);
        int4 iA = ls4[0], iB = ls4[1], iC_ = ls4[2], iD = ls4[3];
        int idxs[16] = {iA.x, iA.y, iA.z, iA.w, iB.x, iB.y, iB.z, iB.w,
                        iC_.x, iC_.y, iC_.z, iC_.w, iD.x, iD.y, iD.z, iD.w};
        float4 acc = make_float4(0.f, 0.f, 0.f, 0.f);
        #pragma unroll
        for (int k = 0; k < 16; k++) {
            float a = ap[k];
            float4 v = *(const float4*)&tile[idxs[k] * 8 + q * 4];
            acc.x = fmaf(a, v.x, acc.x); acc.y = fmaf(a, v.y, acc.y);
            acc.z = fmaf(a, v.z, acc.z); acc.w = fmaf(a, v.w, acc.w);
        }
        {
            float a = ap[16];
            float4 v = *(const float4*)&tile[n * 8 + q * 4];
            acc.x = fmaf(a, v.x, acc.x); acc.y = fmaf(a, v.y, acc.y);
            acc.z = fmaf(a, v.z, acc.z); acc.w = fmaf(a, v.w, acc.w);
        }
        psum[q * 4 + 0] += elu_f(acc.x + bi_s[q * 4 + 0]);
        psum[q * 4 + 1] += elu_f(acc.y + bi_s[q * 4 + 1]);
        psum[q * 4 + 2] += elu_f(acc.z + bi_s[q * 4 + 2]);
        psum[q * 4 + 3] += elu_f(acc.w + bi_s[q * 4 + 3]);
    }
    #pragma unroll
    for (int f = 0; f < 8; f++) {
        float v = psum[f];
        #pragma unroll
        for (int off = 16; off > 0; off >>= 1)
            v += __shfl_down_sync(0xffffffff, v, off);
        if ((tid & 31) == 0 && v != 0.f) atomicAdd(&poolS[f], v);
    }
    __syncthreads();
    if (tid < 8) g_emb[tb * 8 + tid] = poolS[tid] * (1.0f / (float)NPG);
}

// ---------------- LSTM + FC, batch-parallel ----------------
__device__ __forceinline__ float sigmoidf(float x) { return 1.f / (1.f + expf(-x)); }

__global__ __launch_bounds__(512)
void lstm_fc8(const float* __restrict__ w_ih, const float* __restrict__ w_hh,
              const float* __restrict__ b_ih, const float* __restrict__ b_hh,
              const float* __restrict__ w_fc, const float* __restrict__ b_fc,
              float* __restrict__ out) {
    __shared__ float h[128], c[128], gbuf[512], xs[8];
    int b = blockIdx.x;
    int r = threadIdx.x;
    float bias = b_ih[r] + b_hh[r];
    float wi[8];
    #pragma unroll
    for (int k = 0; k < 8; k++) wi[k] = w_ih[r * 8 + k];
    const float4* wh = (const float4*)(w_hh + (size_t)r * 128);
    if (r < 128) { h[r] = 0.f; c[r] = 0.f; }
    __syncthreads();
    for (int t = 0; t < T_STEPS; t++) {
        if (r < 8) xs[r] = g_emb[t * 64 + b * 8 + r];
        __syncthreads();
        float acc = bias;
        #pragma unroll
        for (int k = 0; k < 8; k++) acc = fmaf(xs[k], wi[k], acc);
        const float4* hb = (const float4*)h;
        #pragma unroll 8
        for (int jj = 0; jj < 32; jj++) {
            float4 w4 = wh[jj], h4 = hb[jj];
            acc = fmaf(w4.x, h4.x, acc); acc = fmaf(w4.y, h4.y, acc);
            acc = fmaf(w4.z, h4.z, acc); acc = fmaf(w4.w, h4.w, acc);
        }
        gbuf[r] = acc;
        __syncthreads();
        if (r < 128) {
            float ig = sigmoidf(gbuf[r]);
            float fg = sigmoidf(gbuf[128 + r]);
            float gg = tanhf(gbuf[256 + r]);
            float og = sigmoidf(gbuf[384 + r]);
            float cn = fg * c[r] + ig * gg;
            c[r] = cn;
            h[r] = og * tanhf(cn);
        }
        __syncthreads();
    }
    if (r < 2) {
        float acc = b_fc[r];
        const float* w = w_fc + r * 128;
        #pragma unroll 8
        for (int jj = 0; jj < 128; jj++) acc += h[jj] * w[jj];
        out[b * 2 + r] = acc;
    }
}

// ---------------- host launch ----------------
extern "C" void kernel_launch(void* const* d_in, const int* in_sizes, int n_in,
                              void* d_out, int out_size) {
    const float *x_seq = 0, *W1 = 0, *as1 = 0, *ad1 = 0, *b1 = 0;
    const float *W2 = 0, *as2 = 0, *ad2 = 0, *b2 = 0;
    const float *W3 = 0, *as3 = 0, *ad3 = 0, *b3 = 0;
    const float *W4 = 0, *as4 = 0, *ad4 = 0, *b4 = 0;
    const float *w_ih = 0, *w_hh = 0, *b_ih = 0, *b_hh = 0, *w_fc = 0, *b_fc = 0;
    const int *edge = 0;
    int c1024 = 0, c512 = 0, c256 = 0, c128 = 0, c8 = 0;
    for (int i = 0; i < n_in; i++) {
        const float* p = (const float*)d_in[i];
        switch (in_sizes[i]) {
            case 172800: x_seq = p; break;
            case 276480: edge = (const int*)p; break;
            case 8640:   break;
            case 131072: W2 = p; break;
            case 65536:  w_hh = p; break;
            case 32768:  W3 = p; break;
            case 4096:   w_ih = p; break;
            case 1024:   { if (c1024++ == 0) W1 = p; else W4 = p; } break;
            case 512: { int k = c512++;
                if (k == 0) as1 = p; else if (k == 1) ad1 = p; else if (k == 2) b1 = p;
                else if (k == 3) b_ih = p; else b_hh = p; } break;
            case 256: { int k = c256++;
                if (k == 0) as2 = p; else if (k == 1) ad2 = p; else if (k == 2) b2 = p;
                else w_fc = p; } break;
            case 128: { int k = c128++;
                if (k == 0) as3 = p; else if (k == 1) ad3 = p; else b3 = p; } break;
            case 8: { int k = c8++;
                if (k == 0) as4 = p; else if (k == 1) ad4 = p; else b4 = p; } break;
            case 2: b_fc = p; break;
            default: break;
        }
    }
    const int* src = edge;

    float *bufA, *bufB;
    __half *W2h, *W3h;
    cudaGetSymbolAddress((void**)&bufA, g_bufA);
    cudaGetSymbolAddress((void**)&bufB, g_bufB);
    cudaGetSymbolAddress((void**)&W2h, g_W2h);
    cudaGetSymbolAddress((void**)&W3h, g_W3h);

    const int SM_F32 = (NPG * 32 + NPG * 2 + NPG * 17) * 4;
    const int SM_F16 = (NPG * 16 + NPG * 2 + NPG * 17 + NPG * 16) * 4;
    const int SM_L4  = (1024 + NPG * 8 + NPG * 2 + NPG * 17 + NPG * 16) * 4;
    cudaFuncSetAttribute(fused_gat<8, 32, false>, cudaFuncAttributeMaxDynamicSharedMemorySize, SM_F32);
    cudaFuncSetAttribute(fused_gat<8, 16, true>,  cudaFuncAttributeMaxDynamicSharedMemorySize, SM_F16);
    cudaFuncSetAttribute(l4_fused, cudaFuncAttributeMaxDynamicSharedMemorySize, SM_L4);

    // 1: merged setup (lsrc + fp16 weights + uvec)
    setup_all<<<1181, 256>>>(src, W2, W3, W1, as1, ad1);
    // 2: layer-1 z
    l1_z<<<640, 256>>>(x_seq);
    // 3: L2 GEMM fp16
    l1gemm_fp16<<<dim3(2, TN / 128), 512>>>(W1, b1, W2h, bufA);
    // 4 (PROFILED): GAT layer 2
    fused_gat<8, 32, false><<<T_STEPS * B_GR * 8, 1024, SM_F32>>>(bufA, as2, ad2, b2, bufB);
    // 5: L3 GEMM fp16
    gemm3_fp16<<<dim3(1, TN / 128), 512>>>(bufB, W3h, bufA);
    // 6: GAT layer 3
    fused_gat<8, 16, true><<<T_STEPS * B_GR * 8, 1024, SM_F16>>>(bufA, as3, ad3, b3, bufB);
    // 7: fused layer 4
    l4_fused<<<T_STEPS * B_GR, 1024, SM_L4>>>(bufB, W4, as4, ad4, b4);
    // 8: LSTM + FC (batch-parallel)
    lstm_fc8<<<B_GR, 512>>>(w_ih, w_hh, b_ih, b_hh, w_fc, b_fc, (float*)d_out);
}

// round 17
// speedup vs baseline: 2.3477x; 1.0675x over previous
#include <cuda_runtime.h>
#include <cuda_fp16.h>
#include <math.h>

#define T_STEPS 10
#define B_GR    8
#define NPG     1080
#define N_NODES 8640
#define TN      86400
#define DEG     16

// ---------------- scratch ----------------
__device__ float  g_bufA[(size_t)TN * 128];     // gemm3 out (fp32)
__device__ float  g_bufB[(size_t)TN * 128];     // gat3 out (fp32)
__device__ __half g_Xh[(size_t)TN * 256];       // l1gemm out (fp16)
__device__ __half g_X2h[(size_t)TN * 256];      // gat2 out (fp16)
__device__ float g_z[TN * 16];
__device__ __half g_W2h[512 * 256];
__device__ __half g_W3h[256 * 128];
__device__ float g_emb[T_STEPS * B_GR * 8];
__device__ float g_uv[32];
__device__ int   g_lsrc[N_NODES * 16];

// ---------------- fast exp for x <= 0 ----------------
__device__ __forceinline__ float exp_neg(float x) {
    x = fmaxf(x, -87.0f);
    const float L2E = 1.4426950408889634f;
    float z = fmaf(x, L2E, 12582912.0f);
    int   ei = __float_as_int(z);
    float n = z - 12582912.0f;
    float f = fmaf(x, L2E, -n);
    float r = fmaf(1.5403530e-4f, f, 1.3333558e-3f);
    r = fmaf(r, f, 9.6181291e-3f);
    r = fmaf(r, f, 5.5504109e-2f);
    r = fmaf(r, f, 2.4022651e-1f);
    r = fmaf(r, f, 6.9314718e-1f);
    r = fmaf(r, f, 1.0f);
    float s = __int_as_float((ei + 127) << 23);
    return r * s;
}
__device__ __forceinline__ float elu_f(float v) { return v > 0.f ? v : exp_neg(v) - 1.f; }
__device__ __forceinline__ float lrelu(float e) { return e >= 0.f ? e : 0.2f * e; }

// ---------------- merged setup ----------------
__global__ void setup_all(const int* __restrict__ src, const float* __restrict__ W2,
                          const float* __restrict__ W3, const float* __restrict__ W1,
                          const float* __restrict__ as1, const float* __restrict__ ad1) {
    int bid = blockIdx.x, tid = threadIdx.x;
    if (bid < 540) {
        int i = bid * 256 + tid;
        int b = i / (NPG * 16);
        g_lsrc[i] = src[i] - b * NPG;
    } else if (bid < 1052) {
        int i = (bid - 540) * 256 + tid;
        g_W2h[i] = __float2half_rn(W2[i]);
    } else if (bid < 1180) {
        int i = (bid - 1052) * 256 + tid;
        g_W3h[i] = __float2half_rn(W3[i]);
    } else if (tid < 32) {
        int d = tid >> 4, h = (tid >> 1) & 7, f = tid & 1;
        const float* a = d ? ad1 : as1;
        float s = 0.f;
        #pragma unroll
        for (int c = 0; c < 64; c++) s += W1[f * 512 + h * 64 + c] * a[h * 64 + c];
        g_uv[tid] = s;
    }
}

// ---------------- layer 1: x -> z[TN,16] ----------------
__global__ __launch_bounds__(256)
void l1_z(const float* __restrict__ x) {
    __shared__ float xs[NPG * 2];
    __shared__ float es_s[NPG * 8];
    __shared__ float uvS[32];
    int blk = blockIdx.x;
    int chunk = blk & 7;
    int tb = blk >> 3;
    int b = tb & 7, t = tb >> 3;
    int base = t * N_NODES + b * NPG;
    int tid = threadIdx.x;
    if (tid < 32) uvS[tid] = g_uv[tid];
    for (int i = tid; i < NPG * 2; i += 256) xs[i] = x[(size_t)base * 2 + i];
    __syncthreads();
    for (int task = tid; task < NPG * 8; task += 256) {
        int n = task >> 3, h = task & 7;
        es_s[task] = fmaf(xs[n * 2], uvS[h * 2], xs[n * 2 + 1] * uvS[h * 2 + 1]);
    }
    __syncthreads();
    int n0 = chunk * 135;
    for (int task = tid; task < 135 * 8; task += 256) {
        int nl = task >> 3, h = task & 7;
        int n = n0 + nl;
        const int4* ls4 = (const int4*)(g_lsrc + ((size_t)b * NPG + n) * 16);
        int4 iA = ls4[0], iB = ls4[1], iC = ls4[2], iD = ls4[3];
        int idxs[16] = {iA.x, iA.y, iA.z, iA.w, iB.x, iB.y, iB.z, iB.w,
                        iC.x, iC.y, iC.z, iC.w, iD.x, iD.y, iD.z, iD.w};
        float ed = fmaf(xs[n * 2], uvS[16 + h * 2], xs[n * 2 + 1] * uvS[17 + h * 2]);
        float ev[17];
        float m = -1e30f;
        #pragma unroll
        for (int k = 0; k < 16; k++) {
            float e = lrelu(es_s[idxs[k] * 8 + h] + ed);
            ev[k] = e; m = fmaxf(m, e);
        }
        { float e = lrelu(es_s[n * 8 + h] + ed); ev[16] = e; m = fmaxf(m, e); }
        float ssum = 0.f;
        #pragma unroll
        for (int k = 0; k < 17; k++) { float v = exp_neg(ev[k] - m); ev[k] = v; ssum += v; }
        float inv = 1.f / (ssum + 1e-16f);
        float z0 = 0.f, z1 = 0.f;
        #pragma unroll
        for (int k = 0; k < 16; k++) {
            float a = ev[k] * inv;
            z0 = fmaf(a, xs[idxs[k] * 2], z0);
            z1 = fmaf(a, xs[idxs[k] * 2 + 1], z1);
        }
        {
            float a = ev[16] * inv;
            z0 = fmaf(a, xs[n * 2], z0);
            z1 = fmaf(a, xs[n * 2 + 1], z1);
        }
        *(float2*)&g_z[(size_t)(base + n) * 16 + h * 2] = make_float2(z0, z1);
    }
}

// ---------------- GEMM macros ----------------
#define MMA_FP16(d, a, b0, b1) \
    asm volatile("mma.sync.aligned.m16n8k16.row.col.f32.f16.f16.f32 " \
        "{%0,%1,%2,%3}, {%4,%5,%6,%7}, {%8,%9}, {%0,%1,%2,%3};" \
        : "+f"(d[0]), "+f"(d[1]), "+f"(d[2]), "+f"(d[3]) \
        : "r"(a[0]), "r"(a[1]), "r"(a[2]), "r"(a[3]), "r"(b0), "r"(b1))

#define LDMX4(r, addr) \
    asm volatile("ldmatrix.sync.aligned.m8n8.x4.shared.b16 {%0,%1,%2,%3}, [%4];" \
        : "=r"(r[0]), "=r"(r[1]), "=r"(r[2]), "=r"(r[3]) : "r"(addr))

#define LDMX4T(r, addr) \
    asm volatile("ldmatrix.sync.aligned.m8n8.x4.trans.shared.b16 {%0,%1,%2,%3}, [%4];" \
        : "=r"(r[0]), "=r"(r[1]), "=r"(r[2]), "=r"(r[3]) : "r"(addr))

#define CP16(dst, src) \
    asm volatile("cp.async.cg.shared.global [%0], [%1], 16;" :: "r"(dst), "l"(src))
#define CP_COMMIT asm volatile("cp.async.commit_group;")
#define CP_WAIT1  asm volatile("cp.async.wait_group 1;")
#define CP_WAIT0  asm volatile("cp.async.wait_group 0;")

#define ASTR 24
#define BSTR2 136

struct alignas(8) US4 { unsigned short v[4]; };

// ---------------- L2 GEMM fp16: A from z, C written as fp16 ----------------
__global__ __launch_bounds__(512)
void l1gemm_fp16(const float* __restrict__ W1, const float* __restrict__ b1,
                 const __half* __restrict__ W, __half* __restrict__ Ch) {
    const int Nc = 256;
    __shared__ alignas(16) unsigned short sA[128 * ASTR];
    __shared__ alignas(16) unsigned short sB[3][16 * BSTR2];
    __shared__ float zs[128][16];
    __shared__ float W1s[1024], b1s[512];
    const int tid = threadIdx.x;
    const int lane = tid & 31, wid = tid >> 5;
    const int warpM = wid & 3, warpN = wid >> 2;
    const int rb = blockIdx.y * 128, cb = blockIdx.x * 128;
    const int j = tid & 255;
    const int brow = j >> 4, bcol = (j & 15) * 8;
    const bool doB = (tid < 256);
    const __half* bptr = W + (size_t)brow * Nc + cb + bcol;
    unsigned sb_dst[3];
    #pragma unroll
    for (int s = 0; s < 3; s++)
        sb_dst[s] = (unsigned)__cvta_generic_to_shared(&sB[s][brow * BSTR2 + bcol]);
    {
        int row = tid >> 2, q = tid & 3;
        *(float4*)&zs[row][q * 4] = *(const float4*)(g_z + (size_t)(rb + row) * 16 + q * 4);
    }
    for (int i = tid; i < 1024; i += 512) W1s[i] = W1[i];
    if (tid < 512) b1s[tid] = b1[tid];
    if (doB) { CP16(sb_dst[0], bptr); }
    CP_COMMIT;
    if (doB) { CP16(sb_dst[1], bptr + (size_t)16 * Nc); }
    CP_COMMIT;
    __syncthreads();

    const int arow = tid >> 2, ac0 = (tid & 3) * 4;
    const int a_r = (lane & 15);
    const int a_c = (lane >> 4) * 8;
    const int b_k = (lane & 7) + (lane & 8);
    const int b_n = (lane & 16) >> 1;
    float acc[2][4][4] = {};
    const int nk = 32;

    for (int ck = 0; ck < nk; ck++) {
        {
            int h = ck >> 2;
            float z0 = zs[arow][h * 2], z1 = zs[arow][h * 2 + 1];
            US4 hv;
            #pragma unroll
            for (int i = 0; i < 4; i++) {
                int k = ck * 16 + ac0 + i;
                float v = elu_f(fmaf(z0, W1s[k], fmaf(z1, W1s[512 + k], b1s[k])));
                __half hh = __float2half_rn(v);
                hv.v[i] = *(unsigned short*)&hh;
            }
            *(US4*)&sA[arow * ASTR + ac0] = hv;
        }
        if (ck + 1 < nk) { CP_WAIT1; } else { CP_WAIT0; }
        __syncthreads();
        if (ck + 2 < nk) {
            int buf = (ck + 2) % 3;
            if (doB) { CP16(sb_dst[buf], bptr + (size_t)((ck + 2) * 16) * Nc); }
            CP_COMMIT;
        }
        int p = ck % 3;
        unsigned ah[2][4];
        #pragma unroll
        for (int ma = 0; ma < 2; ma++) {
            int r = warpM * 32 + ma * 16 + a_r;
            unsigned ad = (unsigned)__cvta_generic_to_shared(&sA[r * ASTR + a_c]);
            LDMX4(ah[ma], ad);
        }
        unsigned bh[4][2];
        #pragma unroll
        for (int g = 0; g < 2; g++) {
            int n0 = warpN * 32 + g * 16 + b_n;
            unsigned ad = (unsigned)__cvta_generic_to_shared(&sB[p][b_k * BSTR2 + n0]);
            unsigned th[4];
            LDMX4T(th, ad);
            bh[g * 2][0] = th[0]; bh[g * 2][1] = th[1];
            bh[g * 2 + 1][0] = th[2]; bh[g * 2 + 1][1] = th[3];
        }
        #pragma unroll
        for (int ma = 0; ma < 2; ma++)
            #pragma unroll
            for (int na = 0; na < 4; na++)
                MMA_FP16(acc[ma][na], ah[ma], bh[na][0], bh[na][1]);
        __syncthreads();
    }
    #pragma unroll
    for (int ma = 0; ma < 2; ma++)
        #pragma unroll
        for (int na = 0; na < 4; na++) {
            int r0 = rb + warpM * 32 + ma * 16 + (lane >> 2);
            int c = cb + warpN * 32 + na * 8 + (lane & 3) * 2;
            *(__half2*)(Ch + (size_t)r0 * Nc + c)       = __floats2half2_rn(acc[ma][na][0], acc[ma][na][1]);
            *(__half2*)(Ch + (size_t)(r0 + 8) * Nc + c) = __floats2half2_rn(acc[ma][na][2], acc[ma][na][3]);
        }
}

// ---------------- L3 GEMM fp16: A already fp16, pure cp.async staging ----------------
__global__ __launch_bounds__(512)
void gemm3_fp16(const __half* __restrict__ Ah, const __half* __restrict__ W,
                float* __restrict__ C) {
    const int K = 256, Nc = 128;
    __shared__ alignas(16) unsigned short sA[3][128 * ASTR];
    __shared__ alignas(16) unsigned short sB[3][16 * BSTR2];
    const int tid = threadIdx.x;
    const int lane = tid & 31, wid = tid >> 5;
    const int warpM = wid & 3, warpN = wid >> 2;
    const int rb = blockIdx.y * 128;
    const bool doB = (tid < 256);
    int j = tid & 255;
    // B staging (tid<256): 16 rows x 128 halves
    const int brow = j >> 4, bcol = (j & 15) * 8;
    const __half* bptr = W + (size_t)brow * Nc + bcol;
    // A staging (tid>=256): 128 rows x 16 halves per chunk = 2 CP16 per row
    const int arow = j >> 1, aseg = j & 1;
    const __half* aptr = Ah + (size_t)(rb + arow) * K + aseg * 8;
    unsigned sb_dst[3], sa_dst[3];
    #pragma unroll
    for (int s = 0; s < 3; s++) {
        sb_dst[s] = (unsigned)__cvta_generic_to_shared(&sB[s][brow * BSTR2 + bcol]);
        sa_dst[s] = (unsigned)__cvta_generic_to_shared(&sA[s][arow * ASTR + aseg * 8]);
    }
    if (doB) { CP16(sb_dst[0], bptr); } else { CP16(sa_dst[0], aptr); }
    CP_COMMIT;
    if (doB) { CP16(sb_dst[1], bptr + (size_t)16 * Nc); } else { CP16(sa_dst[1], aptr + 16); }
    CP_COMMIT;
    const int a_r = (lane & 15);
    const int a_c = (lane >> 4) * 8;
    const int b_k = (lane & 7) + (lane & 8);
    const int b_n = (lane & 16) >> 1;
    float acc[2][4][4] = {};
    const int nk = 16;

    for (int ck = 0; ck < nk; ck++) {
        if (ck + 1 < nk) { CP_WAIT1; } else { CP_WAIT0; }
        __syncthreads();
        if (ck + 2 < nk) {
            int buf = (ck + 2) % 3;
            if (doB) { CP16(sb_dst[buf], bptr + (size_t)((ck + 2) * 16) * Nc); }
            else     { CP16(sa_dst[buf], aptr + (ck + 2) * 16); }
            CP_COMMIT;
        }
        int p = ck % 3;
        unsigned ah[2][4];
        #pragma unroll
        for (int ma = 0; ma < 2; ma++) {
            int r = warpM * 32 + ma * 16 + a_r;
            unsigned ad = (unsigned)__cvta_generic_to_shared(&sA[p][r * ASTR + a_c]);
            LDMX4(ah[ma], ad);
        }
        unsigned bh[4][2];
        #pragma unroll
        for (int g = 0; g < 2; g++) {
            int n0 = warpN * 32 + g * 16 + b_n;
            unsigned ad = (unsigned)__cvta_generic_to_shared(&sB[p][b_k * BSTR2 + n0]);
            unsigned th[4];
            LDMX4T(th, ad);
            bh[g * 2][0] = th[0]; bh[g * 2][1] = th[1];
            bh[g * 2 + 1][0] = th[2]; bh[g * 2 + 1][1] = th[3];
        }
        #pragma unroll
        for (int ma = 0; ma < 2; ma++)
            #pragma unroll
            for (int na = 0; na < 4; na++)
                MMA_FP16(acc[ma][na], ah[ma], bh[na][0], bh[na][1]);
        __syncthreads();
    }
    #pragma unroll
    for (int ma = 0; ma < 2; ma++)
        #pragma unroll
        for (int na = 0; na < 4; na++) {
            int r0 = rb + warpM * 32 + ma * 16 + (lane >> 2);
            int c = warpN * 32 + na * 8 + (lane & 3) * 2;
            *(float2*)(C + (size_t)r0 * Nc + c)       = make_float2(acc[ma][na][0], acc[ma][na][1]);
            *(float2*)(C + (size_t)(r0 + 8) * Nc + c) = make_float2(acc[ma][na][2], acc[ma][na][3]);
        }
}

// ---------------- fused GAT layer 2: half in, half out ----------------
__global__ __launch_bounds__(1024, 1)
void fused_gat2_h(const __half* __restrict__ Yh, const float* __restrict__ as_,
                  const float* __restrict__ ad_, const float* __restrict__ bias,
                  __half* __restrict__ Xouth) {
    extern __shared__ float sm[];
    const int H = 8, C = 32, HC = 256, Q = 8;
    float* tile   = sm;                     // NPG*32
    float* es_s   = tile + NPG * C;
    float* ed_s   = es_s + NPG;
    float* alphaS = ed_s + NPG;
    __shared__ float as_s[32], ad_s[32], bi_s[32];
    int blk = blockIdx.x;
    int h = blk % H;
    int tb = blk / H;
    int b = tb % B_GR;
    int t = tb / B_GR;
    int base = t * N_NODES + b * NPG;
    int tid = threadIdx.x;
    const int* lg = g_lsrc + (size_t)b * NPG * 16;
    if (tid < C) { as_s[tid] = as_[h * C + tid]; ad_s[tid] = ad_[h * C + tid]; bi_s[tid] = bias[h * C + tid]; }
    // stage tile: convert fp16 -> fp32
    for (int i = tid; i < NPG * Q; i += blockDim.x) {
        int n = i / Q, q = i % Q;
        const __half2* src2 = (const __half2*)(Yh + (size_t)(base + n) * HC + h * C + q * 4);
        float2 f0 = __half22float2(src2[0]);
        float2 f1 = __half22float2(src2[1]);
        *(float4*)&tile[n * C + q * 4] = make_float4(f0.x, f0.y, f1.x, f1.y);
    }
    __syncthreads();
    for (int n = tid; n < NPG; n += blockDim.x) {
        const float* tn = tile + n * C;
        int rot1 = tid & (Q - 1);
        float se = 0.f, de = 0.f;
        #pragma unroll
        for (int jj = 0; jj < Q; jj++) {
            int q = (jj + rot1) & (Q - 1);
            float4 v = *(const float4*)&tn[q * 4];
            float4 a = *(const float4*)&as_s[q * 4];
            float4 d = *(const float4*)&ad_s[q * 4];
            se = fmaf(v.x, a.x, fmaf(v.y, a.y, fmaf(v.z, a.z, fmaf(v.w, a.w, se))));
            de = fmaf(v.x, d.x, fmaf(v.y, d.y, fmaf(v.z, d.z, fmaf(v.w, d.w, de))));
        }
        es_s[n] = se; ed_s[n] = de;
    }
    __syncthreads();
    for (int n = tid; n < NPG; n += blockDim.x) {
        const int4* ls4 = (const int4*)(lg + n * 16);
        int4 iA = ls4[0], iB = ls4[1], iC_ = ls4[2], iD = ls4[3];
        int idxs[16] = {iA.x, iA.y, iA.z, iA.w, iB.x, iB.y, iB.z, iB.w,
                        iC_.x, iC_.y, iC_.z, iC_.w, iD.x, iD.y, iD.z, iD.w};
        float ed = ed_s[n];
        float m = lrelu(es_s[n] + ed);
        #pragma unroll
        for (int k = 0; k < 16; k++) m = fmaxf(m, lrelu(es_s[idxs[k]] + ed));
        float* ap = alphaS + n * 17;
        float ssum = 0.f;
        #pragma unroll
        for (int k = 0; k < 16; k++) {
            float v = exp_neg(lrelu(es_s[idxs[k]] + ed) - m);
            ap[k] = v; ssum += v;
        }
        { float v = exp_neg(lrelu(es_s[n] + ed) - m); ap[16] = v; ssum += v; }
        float inv = 1.f / (ssum + 1e-16f);
        #pragma unroll
        for (int k = 0; k < 17; k++) ap[k] *= inv;
    }
    __syncthreads();
    for (int task = tid; task < NPG * Q; task += blockDim.x) {
        int n = task / Q, q = task % Q;
        const float* ap = alphaS + n * 17;
        const int4* ls4 = (const int4*)(lg + n * 16);
        int4 iA = ls4[0], iB = ls4[1], iC_ = ls4[2], iD = ls4[3];
        int idxs[16] = {iA.x, iA.y, iA.z, iA.w, iB.x, iB.y, iB.z, iB.w,
                        iC_.x, iC_.y, iC_.z, iC_.w, iD.x, iD.y, iD.z, iD.w};
        float4 acc = make_float4(0.f, 0.f, 0.f, 0.f);
        #pragma unroll
        for (int k = 0; k < 16; k++) {
            float a = ap[k];
            float4 v = *(const float4*)&tile[idxs[k] * C + q * 4];
            acc.x = fmaf(a, v.x, acc.x); acc.y = fmaf(a, v.y, acc.y);
            acc.z = fmaf(a, v.z, acc.z); acc.w = fmaf(a, v.w, acc.w);
        }
        {
            float a = ap[16];
            float4 v = *(const float4*)&tile[n * C + q * 4];
            acc.x = fmaf(a, v.x, acc.x); acc.y = fmaf(a, v.y, acc.y);
            acc.z = fmaf(a, v.z, acc.z); acc.w = fmaf(a, v.w, acc.w);
        }
        float o0 = elu_f(acc.x + bi_s[q * 4 + 0]);
        float o1 = elu_f(acc.y + bi_s[q * 4 + 1]);
        float o2 = elu_f(acc.z + bi_s[q * 4 + 2]);
        float o3 = elu_f(acc.w + bi_s[q * 4 + 3]);
        __half2* dst2 = (__half2*)(Xouth + (size_t)(base + n) * HC + h * C + q * 4);
        dst2[0] = __floats2half2_rn(o0, o1);
        dst2[1] = __floats2half2_rn(o2, o3);
    }
}

// ---------------- fused GAT layer 3 (fp32 in/out, R15 form) ----------------
__global__ __launch_bounds__(1024, 1)
void fused_gat3(const float* __restrict__ Y, const float* __restrict__ as_,
                const float* __restrict__ ad_, const float* __restrict__ bias,
                float* __restrict__ Xout) {
    extern __shared__ float sm[];
    const int H = 8, C = 16, HC = 128, Q = 4;
    float* tile   = sm;
    float* es_s   = tile + NPG * C;
    float* ed_s   = es_s + NPG;
    float* alphaS = ed_s + NPG;
    int*   lsrcS  = (int*)(alphaS + NPG * 17);
    __shared__ float as_s[16], ad_s[16], bi_s[16];
    int blk = blockIdx.x;
    int h = blk % H;
    int tb = blk / H;
    int b = tb % B_GR;
    int t = tb / B_GR;
    int base = t * N_NODES + b * NPG;
    int tid = threadIdx.x;
    const int* lg = g_lsrc + (size_t)b * NPG * 16;
    if (tid < C) { as_s[tid] = as_[h * C + tid]; ad_s[tid] = ad_[h * C + tid]; bi_s[tid] = bias[h * C + tid]; }
    for (int i = tid; i < NPG * Q; i += blockDim.x) {
        int n = i / Q, q = i % Q;
        *(float4*)&tile[n * C + q * 4] =
            *(const float4*)(Y + (size_t)(base + n) * HC + h * C + q * 4);
    }
    for (int i = tid; i < NPG * 4; i += blockDim.x)
        ((int4*)lsrcS)[i] = ((const int4*)lg)[i];
    __syncthreads();
    for (int n = tid; n < NPG; n += blockDim.x) {
        const float* tn = tile + n * C;
        int rot1 = tid & (Q - 1);
        float se = 0.f, de = 0.f;
        #pragma unroll
        for (int jj = 0; jj < Q; jj++) {
            int q = (jj + rot1) & (Q - 1);
            float4 v = *(const float4*)&tn[q * 4];
            float4 a = *(const float4*)&as_s[q * 4];
            float4 d = *(const float4*)&ad_s[q * 4];
            se = fmaf(v.x, a.x, fmaf(v.y, a.y, fmaf(v.z, a.z, fmaf(v.w, a.w, se))));
            de = fmaf(v.x, d.x, fmaf(v.y, d.y, fmaf(v.z, d.z, fmaf(v.w, d.w, de))));
        }
        es_s[n] = se; ed_s[n] = de;
    }
    __syncthreads();
    for (int n = tid; n < NPG; n += blockDim.x) {
        const int4* ls4 = (const int4*)(lsrcS + n * 16);
        int4 iA = ls4[0], iB = ls4[1], iC_ = ls4[2], iD = ls4[3];
        int idxs[16] = {iA.x, iA.y, iA.z, iA.w, iB.x, iB.y, iB.z, iB.w,
                        iC_.x, iC_.y, iC_.z, iC_.w, iD.x, iD.y, iD.z, iD.w};
        float ed = ed_s[n];
        float m = lrelu(es_s[n] + ed);
        #pragma unroll
        for (int k = 0; k < 16; k++) m = fmaxf(m, lrelu(es_s[idxs[k]] + ed));
        float* ap = alphaS + n * 17;
        float ssum = 0.f;
        #pragma unroll
        for (int k = 0; k < 16; k++) {
            float v = exp_neg(lrelu(es_s[idxs[k]] + ed) - m);
            ap[k] = v; ssum += v;
        }
        { float v = exp_neg(lrelu(es_s[n] + ed) - m); ap[16] = v; ssum += v; }
        float inv = 1.f / (ssum + 1e-16f);
        #pragma unroll
        for (int k = 0; k < 17; k++) ap[k] *= inv;
    }
    __syncthreads();
    for (int task = tid; task < NPG * Q; task += blockDim.x) {
        int n = task / Q, q = task % Q;
        const float* ap = alphaS + n * 17;
        const int4* ls4 = (const int4*)(lsrcS + n * 16);
        int4 iA = ls4[0], iB = ls4[1], iC_ = ls4[2], iD = ls4[3];
        int idxs[16] = {iA.x, iA.y, iA.z, iA.w, iB.x, iB.y, iB.z, iB.w,
                        iC_.x, iC_.y, iC_.z, iC_.w, iD.x, iD.y, iD.z, iD.w};
        float4 acc = make_float4(0.f, 0.f, 0.f, 0.f);
        #pragma unroll
        for (int k = 0; k < 16; k++) {
            float a = ap[k];
            float4 v = *(const float4*)&tile[idxs[k] * C + q * 4];
            acc.x = fmaf(a, v.x, acc.x); acc.y = fmaf(a, v.y, acc.y);
            acc.z = fmaf(a, v.z, acc.z); acc.w = fmaf(a, v.w, acc.w);
        }
        {
            float a = ap[16];
            float4 v = *(const float4*)&tile[n * C + q * 4];
            acc.x = fmaf(a, v.x, acc.x); acc.y = fmaf(a, v.y, acc.y);
            acc.z = fmaf(a, v.z, acc.z); acc.w = fmaf(a, v.w, acc.w);
        }
        float4 o;
        o.x = elu_f(acc.x + bi_s[q * 4 + 0]);
        o.y = elu_f(acc.y + bi_s[q * 4 + 1]);
        o.z = elu_f(acc.z + bi_s[q * 4 + 2]);
        o.w = elu_f(acc.w + bi_s[q * 4 + 3]);
        *(float4*)(Xout + (size_t)(base + n) * HC + h * C + q * 4) = o;
    }
}

// ---------------- fused layer 4: GEMM + GAT + pool ----------------
__global__ __launch_bounds__(1024, 1)
void l4_fused(const float* __restrict__ X, const float* __restrict__ W4,
              const float* __restrict__ as4, const float* __restrict__ ad4,
              const float* __restrict__ b4) {
    extern __shared__ float sm[];
    float* w4s    = sm;
    float* tile   = w4s + 1024;
    float* es_s   = tile + NPG * 8;
    float* ed_s   = es_s + NPG;
    float* alphaS = ed_s + NPG;
    int*   lsrcS  = (int*)(alphaS + NPG * 17);
    __shared__ float as_s[8], ad_s[8], bi_s[8];
    __shared__ float poolS[8];
    int tb = blockIdx.x;
    int b = tb % B_GR;
    int t = tb / B_GR;
    int base = t * N_NODES + b * NPG;
    int tid = threadIdx.x;
    if (tid < 8) { as_s[tid] = as4[tid]; ad_s[tid] = ad4[tid]; bi_s[tid] = b4[tid]; poolS[tid] = 0.f; }
    for (int i = tid; i < 1024; i += 1024) w4s[i] = W4[i];
    {
        const int* lg = g_lsrc + (size_t)b * NPG * 16;
        for (int i = tid; i < NPG * 4; i += 1024)
            ((int4*)lsrcS)[i] = ((const int4*)lg)[i];
    }
    __syncthreads();
    for (int n = tid; n < NPG; n += 1024) {
        const float4* xr = (const float4*)(X + (size_t)(base + n) * 128);
        float4 a0 = make_float4(0, 0, 0, 0), a1 = make_float4(0, 0, 0, 0);
        #pragma unroll 8
        for (int k4 = 0; k4 < 32; k4++) {
            float4 xv = xr[k4];
            float xsv[4] = {xv.x, xv.y, xv.z, xv.w};
            #pragma unroll
            for (int kk = 0; kk < 4; kk++) {
                float xs = xsv[kk];
                float4 w0 = *(const float4*)&w4s[(k4 * 4 + kk) * 8];
                float4 w1 = *(const float4*)&w4s[(k4 * 4 + kk) * 8 + 4];
                a0.x = fmaf(xs, w0.x, a0.x); a0.y = fmaf(xs, w0.y, a0.y);
                a0.z = fmaf(xs, w0.z, a0.z); a0.w = fmaf(xs, w0.w, a0.w);
                a1.x = fmaf(xs, w1.x, a1.x); a1.y = fmaf(xs, w1.y, a1.y);
                a1.z = fmaf(xs, w1.z, a1.z); a1.w = fmaf(xs, w1.w, a1.w);
            }
        }
        *(float4*)&tile[n * 8] = a0;
        *(float4*)&tile[n * 8 + 4] = a1;
    }
    __syncthreads();
    for (int n = tid; n < NPG; n += 1024) {
        const float* tn = tile + n * 8;
        float se = 0.f, de = 0.f;
        #pragma unroll
        for (int q = 0; q < 2; q++) {
            float4 v = *(const float4*)&tn[q * 4];
            float4 a = *(const float4*)&as_s[q * 4];
            float4 d = *(const float4*)&ad_s[q * 4];
            se = fmaf(v.x, a.x, fmaf(v.y, a.y, fmaf(v.z, a.z, fmaf(v.w, a.w, se))));
            de = fmaf(v.x, d.x, fmaf(v.y, d.y, fmaf(v.z, d.z, fmaf(v.w, d.w, de))));
        }
        es_s[n] = se; ed_s[n] = de;
    }
    __syncthreads();
    for (int n = tid; n < NPG; n += 1024) {
        const int4* ls4 = (const int4*)(lsrcS + n * 16);
        int4 iA = ls4[0], iB = ls4[1], iC_ = ls4[2], iD = ls4[3];
        int idxs[16] = {iA.x, iA.y, iA.z, iA.w, iB.x, iB.y, iB.z, iB.w,
                        iC_.x, iC_.y, iC_.z, iC_.w, iD.x, iD.y, iD.z, iD.w};
        float ed = ed_s[n];
        float m = lrelu(es_s[n] + ed);
        #pragma unroll
        for (int k = 0; k < 16; k++) m = fmaxf(m, lrelu(es_s[idxs[k]] + ed));
        float* ap = alphaS + n * 17;
        float ssum = 0.f;
        #pragma unroll
        for (int k = 0; k < 16; k++) {
            float v = exp_neg(lrelu(es_s[idxs[k]] + ed) - m);
            ap[k] = v; ssum += v;
        }
        { float v = exp_neg(lrelu(es_s[n] + ed) - m); ap[16] = v; ssum += v; }
        float inv = 1.f / (ssum + 1e-16f);
        #pragma unroll
        for (int k = 0; k < 17; k++) ap[k] *= inv;
    }
    __syncthreads();
    float psum[8] = {};
    for (int task = tid; task < NPG * 2; task += 1024) {
        int n = task >> 1, q = task & 1;
        const float* ap = alphaS + n * 17;
        const int4* ls4 = (const int4*)(lsrcS + n * 16);
        int4 iA = ls4[0], iB = ls4[1], iC_ = ls4[2], iD = ls4[3];
        int idxs[16] = {iA.x, iA.y, iA.z, iA.w, iB.x, iB.y, iB.z, iB.w,
                        iC_.x, iC_.y, iC_.z, iC_.w, iD.x, iD.y, iD.z, iD.w};
        float4 acc = make_float4(0.f, 0.f, 0.f, 0.f);
        #pragma unroll
        for (int k = 0; k < 16; k++) {
            float a = ap[k];
            float4 v = *(const float4*)&tile[idxs[k] * 8 + q * 4];
            acc.x = fmaf(a, v.x, acc.x); acc.y = fmaf(a, v.y, acc.y);
            acc.z = fmaf(a, v.z, acc.z); acc.w = fmaf(a, v.w, acc.w);
        }
        {
            float a = ap[16];
            float4 v = *(const float4*)&tile[n * 8 + q * 4];
            acc.x = fmaf(a, v.x, acc.x); acc.y = fmaf(a, v.y, acc.y);
            acc.z = fmaf(a, v.z, acc.z); acc.w = fmaf(a, v.w, acc.w);
        }
        psum[q * 4 + 0] += elu_f(acc.x + bi_s[q * 4 + 0]);
        psum[q * 4 + 1] += elu_f(acc.y + bi_s[q * 4 + 1]);
        psum[q * 4 + 2] += elu_f(acc.z + bi_s[q * 4 + 2]);
        psum[q * 4 + 3] += elu_f(acc.w + bi_s[q * 4 + 3]);
    }
    #pragma unroll
    for (int f = 0; f < 8; f++) {
        float v = psum[f];
        #pragma unroll
        for (int off = 16; off > 0; off >>= 1)
            v += __shfl_down_sync(0xffffffff, v, off);
        if ((tid & 31) == 0 && v != 0.f) atomicAdd(&poolS[f], v);
    }
    __syncthreads();
    if (tid < 8) g_emb[tb * 8 + tid] = poolS[tid] * (1.0f / (float)NPG);
}

// ---------------- LSTM + FC, batch-parallel ----------------
__device__ __forceinline__ float sigmoidf(float x) { return 1.f / (1.f + expf(-x)); }

__global__ __launch_bounds__(512)
void lstm_fc8(const float* __restrict__ w_ih, const float* __restrict__ w_hh,
              const float* __restrict__ b_ih, const float* __restrict__ b_hh,
              const float* __restrict__ w_fc, const float* __restrict__ b_fc,
              float* __restrict__ out) {
    __shared__ float h[128], c[128], gbuf[512], xs[8];
    int b = blockIdx.x;
    int r = threadIdx.x;
    float bias = b_ih[r] + b_hh[r];
    float wi[8];
    #pragma unroll
    for (int k = 0; k < 8; k++) wi[k] = w_ih[r * 8 + k];
    const float4* wh = (const float4*)(w_hh + (size_t)r * 128);
    if (r < 128) { h[r] = 0.f; c[r] = 0.f; }
    __syncthreads();
    for (int t = 0; t < T_STEPS; t++) {
        if (r < 8) xs[r] = g_emb[t * 64 + b * 8 + r];
        __syncthreads();
        float acc = bias;
        #pragma unroll
        for (int k = 0; k < 8; k++) acc = fmaf(xs[k], wi[k], acc);
        const float4* hb = (const float4*)h;
        #pragma unroll 8
        for (int jj = 0; jj < 32; jj++) {
            float4 w4 = wh[jj], h4 = hb[jj];
            acc = fmaf(w4.x, h4.x, acc); acc = fmaf(w4.y, h4.y, acc);
            acc = fmaf(w4.z, h4.z, acc); acc = fmaf(w4.w, h4.w, acc);
        }
        gbuf[r] = acc;
        __syncthreads();
        if (r < 128) {
            float ig = sigmoidf(gbuf[r]);
            float fg = sigmoidf(gbuf[128 + r]);
            float gg = tanhf(gbuf[256 + r]);
            float og = sigmoidf(gbuf[384 + r]);
            float cn = fg * c[r] + ig * gg;
            c[r] = cn;
            h[r] = og * tanhf(cn);
        }
        __syncthreads();
    }
    if (r < 2) {
        float acc = b_fc[r];
        const float* w = w_fc + r * 128;
        #pragma unroll 8
        for (int jj = 0; jj < 128; jj++) acc += h[jj] * w[jj];
        out[b * 2 + r] = acc;
    }
}

// ---------------- host launch ----------------
extern "C" void kernel_launch(void* const* d_in, const int* in_sizes, int n_in,
                              void* d_out, int out_size) {
    const float *x_seq = 0, *W1 = 0, *as1 = 0, *ad1 = 0, *b1 = 0;
    const float *W2 = 0, *as2 = 0, *ad2 = 0, *b2 = 0;
    const float *W3 = 0, *as3 = 0, *ad3 = 0, *b3 = 0;
    const float *W4 = 0, *as4 = 0, *ad4 = 0, *b4 = 0;
    const float *w_ih = 0, *w_hh = 0, *b_ih = 0, *b_hh = 0, *w_fc = 0, *b_fc = 0;
    const int *edge = 0;
    int c1024 = 0, c512 = 0, c256 = 0, c128 = 0, c8 = 0;
    for (int i = 0; i < n_in; i++) {
        const float* p = (const float*)d_in[i];
        switch (in_sizes[i]) {
            case 172800: x_seq = p; break;
            case 276480: edge = (const int*)p; break;
            case 8640:   break;
            case 131072: W2 = p; break;
            case 65536:  w_hh = p; break;
            case 32768:  W3 = p; break;
            case 4096:   w_ih = p; break;
            case 1024:   { if (c1024++ == 0) W1 = p; else W4 = p; } break;
            case 512: { int k = c512++;
                if (k == 0) as1 = p; else if (k == 1) ad1 = p; else if (k == 2) b1 = p;
                else if (k == 3) b_ih = p; else b_hh = p; } break;
            case 256: { int k = c256++;
                if (k == 0) as2 = p; else if (k == 1) ad2 = p; else if (k == 2) b2 = p;
                else w_fc = p; } break;
            case 128: { int k = c128++;
                if (k == 0) as3 = p; else if (k == 1) ad3 = p; else b3 = p; } break;
            case 8: { int k = c8++;
                if (k == 0) as4 = p; else if (k == 1) ad4 = p; else b4 = p; } break;
            case 2: b_fc = p; break;
            default: break;
        }
    }
    const int* src = edge;

    float *bufA, *bufB;
    __half *W2h, *W3h, *Xh, *X2h;
    cudaGetSymbolAddress((void**)&bufA, g_bufA);
    cudaGetSymbolAddress((void**)&bufB, g_bufB);
    cudaGetSymbolAddress((void**)&W2h, g_W2h);
    cudaGetSymbolAddress((void**)&W3h, g_W3h);
    cudaGetSymbolAddress((void**)&Xh, g_Xh);
    cudaGetSymbolAddress((void**)&X2h, g_X2h);

    const int SM_F32 = (NPG * 32 + NPG * 2 + NPG * 17) * 4;
    const int SM_F16 = (NPG * 16 + NPG * 2 + NPG * 17 + NPG * 16) * 4;
    const int SM_L4  = (1024 + NPG * 8 + NPG * 2 + NPG * 17 + NPG * 16) * 4;
    cudaFuncSetAttribute(fused_gat2_h, cudaFuncAttributeMaxDynamicSharedMemorySize, SM_F32);
    cudaFuncSetAttribute(fused_gat3,   cudaFuncAttributeMaxDynamicSharedMemorySize, SM_F16);
    cudaFuncSetAttribute(l4_fused,     cudaFuncAttributeMaxDynamicSharedMemorySize, SM_L4);

    // 1: merged setup
    setup_all<<<1181, 256>>>(src, W2, W3, W1, as1, ad1);
    // 2: layer-1 z
    l1_z<<<640, 256>>>(x_seq);
    // 3: L2 GEMM fp16 -> fp16 out
    l1gemm_fp16<<<dim3(2, TN / 128), 512>>>(W1, b1, W2h, Xh);
    // 4 (PROFILED): GAT layer 2 (half in / half out)
    fused_gat2_h<<<T_STEPS * B_GR * 8, 1024, SM_F32>>>(Xh, as2, ad2, b2, X2h);
    // 5: L3 GEMM fp16 (A fp16 via cp.async)
    gemm3_fp16<<<dim3(1, TN / 128), 512>>>(X2h, W3h, bufA);
    // 6: GAT layer 3
    fused_gat3<<<T_STEPS * B_GR * 8, 1024, SM_F16>>>(bufA, as3, ad3, b3, bufB);
    // 7: fused layer 4
    l4_fused<<<T_STEPS * B_GR, 1024, SM_L4>>>(bufB, W4, as4, ad4, b4);
    // 8: LSTM + FC
    lstm_fc8<<<B_GR, 512>>>(w_ih, w_hh, b_ih, b_hh, w_fc, b_fc, (float*)d_out);
}